// round 10
// baseline (speedup 1.0000x reference)
#include <cuda_runtime.h>
#include <cuda_bf16.h>
#include <cstdint>

// Problem constants (fixed by the dataset)
#define N_LEFT   100000
#define N_RIGHT  100000
#define N_EDGES  600000
#define EMB      128

// ---------------------------------------------------------------------------
// Device scratch (allocation-free rule: __device__ globals)
// ---------------------------------------------------------------------------
__device__ float g_L   [N_LEFT  * EMB];  // transformed left (scatter source)
__device__ float g_S   [N_RIGHT * EMB];  // transformed right
__device__ float g_conv[N_RIGHT * EMB];  // edge-conv accumulator (zeroed each run)
__device__ float g_Ml[EMB * EMB];        // Wl2 @ Wo1[0:128]
__device__ float g_Mr[EMB * EMB];        // Wr2 @ Wo1[128:256]
__device__ float g_cl[EMB];
__device__ float g_cr[EMB];

// Pre-transposed bf16 hi/lo weight images, [n][k] k-contiguous (B^T layout).
__device__ __align__(16) __nv_bfloat16 g_Wl1T[2][EMB * 64];
__device__ __align__(16) __nv_bfloat16 g_Wr1T[2][EMB * 64];
__device__ __align__(16) __nv_bfloat16 g_MlT [2][EMB * EMB];
__device__ __align__(16) __nv_bfloat16 g_MrT [2][EMB * EMB];
__device__ __align__(16) __nv_bfloat16 g_Wo2T[2][EMB * EMB];

// ---------------------------------------------------------------------------
// PTX helpers (all baseline sm_80+)
// ---------------------------------------------------------------------------
__device__ __forceinline__ void mma16816(float* d, const uint32_t* a, const uint32_t* b) {
    asm volatile(
        "mma.sync.aligned.m16n8k16.row.col.f32.bf16.bf16.f32 "
        "{%0,%1,%2,%3}, {%4,%5,%6,%7}, {%8,%9}, {%0,%1,%2,%3};"
        : "+f"(d[0]), "+f"(d[1]), "+f"(d[2]), "+f"(d[3])
        : "r"(a[0]), "r"(a[1]), "r"(a[2]), "r"(a[3]), "r"(b[0]), "r"(b[1]));
}
__device__ __forceinline__ void ldsm_x4(uint32_t& r0, uint32_t& r1, uint32_t& r2, uint32_t& r3,
                                        uint32_t addr) {
    asm volatile("ldmatrix.sync.aligned.m8n8.x4.shared.b16 {%0,%1,%2,%3}, [%4];"
                 : "=r"(r0), "=r"(r1), "=r"(r2), "=r"(r3) : "r"(addr));
}
__device__ __forceinline__ uint32_t cvta_s(const void* p) {
    return (uint32_t)__cvta_generic_to_shared(p);
}
__device__ __forceinline__ void cp_async16(uint32_t dst, const void* src) {
    asm volatile("cp.async.cg.shared.global [%0], [%1], 16;" :: "r"(dst), "l"(src));
}
__device__ __forceinline__ void cp_commit() {
    asm volatile("cp.async.commit_group;");
}
__device__ __forceinline__ void cp_wait0() {
    asm volatile("cp.async.wait_group 0;");
}

// ---------------------------------------------------------------------------
// MMA stage: acc[MT][4][4] += split3( A[MT*32][K] @ B[128][K]^T )
// smem row stride K+8 (16B-aligned rows, conflict-free ldmatrix).
// ---------------------------------------------------------------------------
template<int K, int MT>
__device__ __forceinline__ void mma_stage(const __nv_bfloat16* __restrict__ Ahi,
                                          const __nv_bfloat16* __restrict__ Alo,
                                          const __nv_bfloat16* __restrict__ Bhi,
                                          const __nv_bfloat16* __restrict__ Blo,
                                          float acc[][4][4],
                                          int warp_m, int warp_n, int lane)
{
    constexpr int SK = K + 8;
    const int tr = lane & 7, quad = lane >> 3;
    const int a_row = warp_m * (MT * 16) + tr + (quad & 1) * 8;
    const int a_col = (quad >> 1) * 8;
    const int b_row = warp_n * 32 + tr + (quad >> 1) * 8;
    const int b_col = (quad & 1) * 8;

    uint32_t aAh = cvta_s(Ahi) + (uint32_t)(a_row * SK + a_col) * 2;
    uint32_t aAl = cvta_s(Alo) + (uint32_t)(a_row * SK + a_col) * 2;
    uint32_t aBh = cvta_s(Bhi) + (uint32_t)(b_row * SK + b_col) * 2;
    uint32_t aBl = cvta_s(Blo) + (uint32_t)(b_row * SK + b_col) * 2;

#pragma unroll
    for (int kc = 0; kc < K / 16; kc++) {
        const uint32_t ko = kc * 32;   // 16 elems = 32 bytes
        uint32_t ah[MT][4], al[MT][4], bh[2][4], bl[2][4];
#pragma unroll
        for (int mt = 0; mt < MT; mt++) {
            const uint32_t mo = (uint32_t)(mt * 16 * SK) * 2 + ko;
            ldsm_x4(ah[mt][0], ah[mt][1], ah[mt][2], ah[mt][3], aAh + mo);
            ldsm_x4(al[mt][0], al[mt][1], al[mt][2], al[mt][3], aAl + mo);
        }
#pragma unroll
        for (int np = 0; np < 2; np++) {
            const uint32_t no = (uint32_t)(np * 16 * SK) * 2 + ko;
            ldsm_x4(bh[np][0], bh[np][1], bh[np][2], bh[np][3], aBh + no);
            ldsm_x4(bl[np][0], bl[np][1], bl[np][2], bl[np][3], aBl + no);
        }
#pragma unroll
        for (int mt = 0; mt < MT; mt++)
#pragma unroll
            for (int nt = 0; nt < 4; nt++) {
                const uint32_t* ph = &bh[nt >> 1][(nt & 1) * 2];
                const uint32_t* pl = &bl[nt >> 1][(nt & 1) * 2];
                mma16816(acc[mt][nt], ah[mt], ph);
                mma16816(acc[mt][nt], ah[mt], pl);
                mma16816(acc[mt][nt], al[mt], ph);
            }
    }
}

// Async copy a [128][K] bf16 image from gmem (packed) into padded smem.
template<int K>
__device__ __forceinline__ void load_B_async(__nv_bfloat16* __restrict__ dst,
                                             const uint4* __restrict__ src, int tid)
{
    constexpr int SK = K + 8;
    constexpr int NV = 128 * K / 8;
#pragma unroll
    for (int i = tid; i < NV; i += 256) {
        const int row = i / (K / 8);
        const int col = (i % (K / 8)) * 8;
        cp_async16(cvta_s(dst + row * SK + col), src + i);
    }
}

// bf16 hi/lo split + smem store helper (2 packed pairs from a float4)
__device__ __forceinline__ void split_store4(__nv_bfloat16* hi, __nv_bfloat16* lo,
                                             int idx, float4 v)
{
    __nv_bfloat16 hx = __float2bfloat16(v.x), hy = __float2bfloat16(v.y);
    __nv_bfloat16 hz = __float2bfloat16(v.z), hw = __float2bfloat16(v.w);
    __nv_bfloat162 h0(hx, hy), h1(hz, hw);
    __nv_bfloat162 l0(__float2bfloat16(v.x - __bfloat162float(hx)),
                      __float2bfloat16(v.y - __bfloat162float(hy)));
    __nv_bfloat162 l1(__float2bfloat16(v.z - __bfloat162float(hz)),
                      __float2bfloat16(v.w - __bfloat162float(hw)));
    *(uint32_t*)(hi + idx)     = *(uint32_t*)&h0;
    *(uint32_t*)(hi + idx + 2) = *(uint32_t*)&h1;
    *(uint32_t*)(lo + idx)     = *(uint32_t*)&l0;
    *(uint32_t*)(lo + idx + 2) = *(uint32_t*)&l1;
}

// Load A[row0..+63][0..K) fp32 from gmem, bf16 hi/lo split, padded smem.
template<int K>
__device__ __forceinline__ void load_A64(__nv_bfloat16* __restrict__ hi,
                                         __nv_bfloat16* __restrict__ lo,
                                         const float* __restrict__ X,
                                         int row0, int M, int tid)
{
    constexpr int SK = K + 8;
    const int row  = tid >> 2;
    const int grow = row0 + row;
    const bool valid = grow < M;
    const float* xr = X + (size_t)grow * K;
    const int cbase = (tid & 3) * (K / 4);
#pragma unroll
    for (int q = 0; q < K / 16; q++) {
        const int c0 = cbase + q * 4;
        float4 v = valid ? *(const float4*)(xr + c0) : make_float4(0.f, 0.f, 0.f, 0.f);
        split_store4(hi, lo, row * SK + c0, v);
    }
}

// ---------------------------------------------------------------------------
// Fused 2-layer MLP (one side per launch), M=64 per CTA, overlaid smem
// (2 CTAs/SM):  C = relu(X @ W1 [+ b1]) @ W2 + b2
// ---------------------------------------------------------------------------
#define K1 64
#define K2 128
#define SK1 (K1 + 8)
#define SK2 (K2 + 8)
#define M_B1H 0
#define M_B1L (128 * SK1)                   // 9216
#define M_A1H (2 * 128 * SK1)               // 18432
#define M_A1L (M_A1H + 64 * SK1)            // 23040
#define M_HH  0
#define M_HL  (64 * SK2)                    // 8704
#define M_B2H 18432
#define M_B2L (M_B2H + 128 * SK2)           // 35840
#define MLP_SMEM_ELEMS (M_B2L + 128 * SK2)  // 53248
#define MLP_SMEM_BYTES (MLP_SMEM_ELEMS * 2) // 106496

__global__ void __launch_bounds__(256, 2)
mlp_kernel(const float* __restrict__ X,
           const uint4* __restrict__ B1hi, const uint4* __restrict__ B1lo,
           const float* __restrict__ bias1,          // may be null
           const uint4* __restrict__ B2hi, const uint4* __restrict__ B2lo,
           const float* __restrict__ bias2,
           float* __restrict__ C, int M)
{
    extern __shared__ __nv_bfloat16 sm[];
    const int tid = threadIdx.x;
    const int wid = tid >> 5, lane = tid & 31;
    const int warp_m = wid >> 2, warp_n = wid & 3;
    const int g = lane >> 2, c = lane & 3;
    const int row0 = blockIdx.x * 64;

    load_B_async<K1>(sm + M_B1H, B1hi, tid);
    load_B_async<K1>(sm + M_B1L, B1lo, tid);
    cp_commit();
    load_A64<K1>(sm + M_A1H, sm + M_A1L, X, row0, M, tid);  // overlaps B1 fetch
    cp_wait0();
    __syncthreads();

    float acc[2][4][4];
#pragma unroll
    for (int mt = 0; mt < 2; mt++)
#pragma unroll
        for (int nt = 0; nt < 4; nt++)
#pragma unroll
            for (int j = 0; j < 4; j++) acc[mt][nt][j] = 0.f;

    mma_stage<K1, 2>(sm + M_A1H, sm + M_A1L, sm + M_B1H, sm + M_B1L,
                     acc, warp_m, warp_n, lane);
    __syncthreads();   // all warps done reading A1/B1

    // prefetch B2 over A1/X region (A1 fully consumed), overlapping epilogue-1
    load_B_async<K2>(sm + M_B2H, B2hi, tid);
    load_B_async<K2>(sm + M_B2L, B2lo, tid);
    cp_commit();

    // epilogue 1: H = relu(acc + b1) -> bf16 hi/lo over B1 region
#pragma unroll
    for (int mt = 0; mt < 2; mt++) {
        const int row = warp_m * 32 + mt * 16 + g;
#pragma unroll
        for (int nt = 0; nt < 4; nt++) {
            const int col = warp_n * 32 + nt * 8 + c * 2;
            float v0 = acc[mt][nt][0], v1 = acc[mt][nt][1];
            float v2 = acc[mt][nt][2], v3 = acc[mt][nt][3];
            if (bias1) {
                float2 b = *(const float2*)(bias1 + col);
                v0 += b.x; v1 += b.y; v2 += b.x; v3 += b.y;
            }
            v0 = fmaxf(v0, 0.f); v1 = fmaxf(v1, 0.f);
            v2 = fmaxf(v2, 0.f); v3 = fmaxf(v3, 0.f);
            __nv_bfloat16 h0 = __float2bfloat16(v0), h1 = __float2bfloat16(v1);
            __nv_bfloat16 h2 = __float2bfloat16(v2), h3 = __float2bfloat16(v3);
            __nv_bfloat162 hp0(h0, h1), hp1(h2, h3);
            __nv_bfloat162 lp0(__float2bfloat16(v0 - __bfloat162float(h0)),
                               __float2bfloat16(v1 - __bfloat162float(h1)));
            __nv_bfloat162 lp1(__float2bfloat16(v2 - __bfloat162float(h2)),
                               __float2bfloat16(v3 - __bfloat162float(h3)));
            *(uint32_t*)(sm + M_HH + row * SK2 + col)       = *(uint32_t*)&hp0;
            *(uint32_t*)(sm + M_HH + (row + 8) * SK2 + col) = *(uint32_t*)&hp1;
            *(uint32_t*)(sm + M_HL + row * SK2 + col)       = *(uint32_t*)&lp0;
            *(uint32_t*)(sm + M_HL + (row + 8) * SK2 + col) = *(uint32_t*)&lp1;
        }
    }
    cp_wait0();
    __syncthreads();

#pragma unroll
    for (int mt = 0; mt < 2; mt++)
#pragma unroll
        for (int nt = 0; nt < 4; nt++)
#pragma unroll
            for (int j = 0; j < 4; j++) acc[mt][nt][j] = 0.f;

    mma_stage<K2, 2>(sm + M_HH, sm + M_HL, sm + M_B2H, sm + M_B2L,
                     acc, warp_m, warp_n, lane);

#pragma unroll
    for (int mt = 0; mt < 2; mt++) {
        const int r = row0 + warp_m * 32 + mt * 16 + g;
#pragma unroll
        for (int nt = 0; nt < 4; nt++) {
            const int col = warp_n * 32 + nt * 8 + c * 2;
            float2 b = *(const float2*)(bias2 + col);
            if (r < M) {
                float2 o0 = make_float2(acc[mt][nt][0] + b.x, acc[mt][nt][1] + b.y);
                *(float2*)(C + (size_t)r * EMB + col) = o0;
            }
            if (r + 8 < M) {
                float2 o1 = make_float2(acc[mt][nt][2] + b.x, acc[mt][nt][3] + b.y);
                *(float2*)(C + (size_t)(r + 8) * EMB + col) = o1;
            }
        }
    }
}

// ---------------------------------------------------------------------------
// Edge scatter: one warp per edge.  conv[dst] += w_e * L[src]  (red.global.v4)
// Depends ONLY on L -> runs concurrently with the right-side MLP.
// ---------------------------------------------------------------------------
__global__ void scatter_kernel(const int* __restrict__ eidx,
                               const float* __restrict__ ew,
                               const float* __restrict__ L,
                               float* __restrict__ conv,
                               int E)
{
    const int warp = (blockIdx.x * blockDim.x + threadIdx.x) >> 5;
    const int lane = threadIdx.x & 31;
    if (warp >= E) return;

    const int src = eidx[warp];
    const int dst = eidx[E + warp];
    const float w = ew[warp];

    float4 v = *(const float4*)(L + (size_t)src * EMB + lane * 4);
    float* out = conv + (size_t)dst * EMB + lane * 4;
    asm volatile("red.global.add.v4.f32 [%0], {%1, %2, %3, %4};"
                 :: "l"(out), "f"(w * v.x), "f"(w * v.y), "f"(w * v.z), "f"(w * v.w)
                 : "memory");
}

// ---------------------------------------------------------------------------
// Output GEMM, M=64 per CTA (2 CTAs/SM):
//   out = relu(S + conv + bo1) @ Wo2 + bo2
// ---------------------------------------------------------------------------
#define F_AH 0
#define F_AL (64 * SK2)                  // 8704
#define F_BH (2 * 64 * SK2)              // 17408
#define F_BL (F_BH + 128 * SK2)          // 34816
#define F_SMEM_ELEMS (F_BL + 128 * SK2)  // 52224
#define F_SMEM_BYTES (F_SMEM_ELEMS * 2)  // 104448

__global__ void __launch_bounds__(256, 2)
out_gemm_kernel(const float* __restrict__ S,
                const float* __restrict__ conv,
                const uint4* __restrict__ Bhi, const uint4* __restrict__ Blo,
                const float* __restrict__ bo1,
                const float* __restrict__ bo2,
                float* __restrict__ C, int M)
{
    extern __shared__ __nv_bfloat16 sm[];
    const int tid = threadIdx.x;
    const int wid = tid >> 5, lane = tid & 31;
    const int warp_m = wid >> 2, warp_n = wid & 3;
    const int g = lane >> 2, c = lane & 3;
    const int row0 = blockIdx.x * 64;

    load_B_async<K2>(sm + F_BH, Bhi, tid);
    load_B_async<K2>(sm + F_BL, Blo, tid);
    cp_commit();

    // A-load: relu(S + conv + bo1), split, store (overlaps B fetch)
    {
        const int row  = tid >> 2;
        const int grow = row0 + row;
        const bool valid = grow < M;
        const float* sr = S    + (size_t)grow * K2;
        const float* vr = conv + (size_t)grow * K2;
        const int cbase = (tid & 3) * (K2 / 4);
#pragma unroll
        for (int q = 0; q < K2 / 16; q++) {
            const int c0 = cbase + q * 4;
            float4 v = make_float4(0.f, 0.f, 0.f, 0.f);
            if (valid) {
                float4 a = *(const float4*)(sr + c0);
                float4 b = *(const float4*)(vr + c0);
                float4 pb = *(const float4*)(bo1 + c0);
                v.x = fmaxf(a.x + b.x + pb.x, 0.f);
                v.y = fmaxf(a.y + b.y + pb.y, 0.f);
                v.z = fmaxf(a.z + b.z + pb.z, 0.f);
                v.w = fmaxf(a.w + b.w + pb.w, 0.f);
            }
            split_store4(sm + F_AH, sm + F_AL, row * SK2 + c0, v);
        }
    }
    cp_wait0();
    __syncthreads();

    float acc[2][4][4];
#pragma unroll
    for (int mt = 0; mt < 2; mt++)
#pragma unroll
        for (int nt = 0; nt < 4; nt++)
#pragma unroll
            for (int j = 0; j < 4; j++) acc[mt][nt][j] = 0.f;

    mma_stage<K2, 2>(sm + F_AH, sm + F_AL, sm + F_BH, sm + F_BL,
                     acc, warp_m, warp_n, lane);

#pragma unroll
    for (int mt = 0; mt < 2; mt++) {
        const int r = row0 + warp_m * 32 + mt * 16 + g;
#pragma unroll
        for (int nt = 0; nt < 4; nt++) {
            const int col = warp_n * 32 + nt * 8 + c * 2;
            float2 b = *(const float2*)(bo2 + col);
            if (r < M) {
                float2 o0 = make_float2(acc[mt][nt][0] + b.x, acc[mt][nt][1] + b.y);
                *(float2*)(C + (size_t)r * EMB + col) = o0;
            }
            if (r + 8 < M) {
                float2 o1 = make_float2(acc[mt][nt][2] + b.x, acc[mt][nt][3] + b.y);
                *(float2*)(C + (size_t)(r + 8) * EMB + col) = o1;
            }
        }
    }
}

// ---------------------------------------------------------------------------
// Weight fusion (matrix rows 0..127, bias row 128) + prep
// ---------------------------------------------------------------------------
__global__ void fuse_wb_kernel(const float* __restrict__ Wl2,
                               const float* __restrict__ Wr2,
                               const float* __restrict__ bl2,
                               const float* __restrict__ br2,
                               const float* __restrict__ Wo1,
                               float* __restrict__ Ml, float* __restrict__ Mr,
                               float* __restrict__ cl, float* __restrict__ cr)
{
    const int i = blockIdx.x, j = threadIdx.x;
    const bool rs = (blockIdx.y != 0);
    const int off = rs ? EMB : 0;
    const float* vec = (i < EMB) ? ((rs ? Wr2 : Wl2) + i * EMB) : (rs ? br2 : bl2);
    float s = 0.f;
#pragma unroll 8
    for (int k = 0; k < EMB; k++)
        s += vec[k] * Wo1[(off + k) * EMB + j];
    if (i < EMB) (rs ? Mr : Ml)[i * EMB + j] = s;
    else         (rs ? cr : cl)[j] = s;
}

__global__ void prep_weights_kernel(const float* __restrict__ Wl1,
                                    const float* __restrict__ Wr1,
                                    const float* __restrict__ Ml,
                                    const float* __restrict__ Mr,
                                    const float* __restrict__ Wo2,
                                    __nv_bfloat16* __restrict__ Wl1T,
                                    __nv_bfloat16* __restrict__ Wr1T,
                                    __nv_bfloat16* __restrict__ MlT,
                                    __nv_bfloat16* __restrict__ MrT,
                                    __nv_bfloat16* __restrict__ Wo2T)
{
    const int n = threadIdx.x;
    const float* W; __nv_bfloat16* T; int K;
    switch (blockIdx.x) {
        case 0: W = Wl1; T = Wl1T; K = 64;  break;
        case 1: W = Wr1; T = Wr1T; K = 64;  break;
        case 2: W = Ml;  T = MlT;  K = 128; break;
        case 3: W = Mr;  T = MrT;  K = 128; break;
        default: W = Wo2; T = Wo2T; K = 128; break;
    }
    __nv_bfloat16* Hi = T;
    __nv_bfloat16* Lo = T + EMB * K;
    for (int k = 0; k < K; k++) {
        float w = W[k * EMB + n];
        __nv_bfloat16 h = __float2bfloat16(w);
        __nv_bfloat16 l = __float2bfloat16(w - __bfloat162float(h));
        Hi[n * K + k] = h;
        Lo[n * K + k] = l;
    }
}

// ---------------------------------------------------------------------------
// Launch
// ---------------------------------------------------------------------------
extern "C" void kernel_launch(void* const* d_in, const int* in_sizes, int n_in,
                              void* d_out, int out_size)
{
    const float* left  = (const float*)d_in[0];
    const int*   eidx  = (const int*)  d_in[1];
    const float* ew    = (const float*)d_in[2];
    const float* right = (const float*)d_in[3];
    const float* Wl1 = (const float*)d_in[5];
    const float* bl1 = (const float*)d_in[6];
    const float* Wl2 = (const float*)d_in[7];
    const float* bl2 = (const float*)d_in[8];
    const float* Wr1 = (const float*)d_in[9];
    const float* Wr2 = (const float*)d_in[10];
    const float* br2 = (const float*)d_in[11];
    const float* Wo1 = (const float*)d_in[12];
    const float* bo1 = (const float*)d_in[13];
    const float* Wo2 = (const float*)d_in[14];
    const float* bo2 = (const float*)d_in[15];

    const int nL = in_sizes[0] / 64;
    const int E  = in_sizes[1] / 2;
    const int nR = in_sizes[3] / 64;
    const int nO = out_size / EMB;

    float *gL, *gS, *gConv, *gMl, *gMr, *gcl, *gcr;
    cudaGetSymbolAddress((void**)&gL,    g_L);
    cudaGetSymbolAddress((void**)&gS,    g_S);
    cudaGetSymbolAddress((void**)&gConv, g_conv);
    cudaGetSymbolAddress((void**)&gMl,   g_Ml);
    cudaGetSymbolAddress((void**)&gMr,   g_Mr);
    cudaGetSymbolAddress((void**)&gcl,   g_cl);
    cudaGetSymbolAddress((void**)&gcr,   g_cr);

    __nv_bfloat16 *wl1t, *wr1t, *mlt, *mrt, *wo2t;
    cudaGetSymbolAddress((void**)&wl1t, g_Wl1T);
    cudaGetSymbolAddress((void**)&wr1t, g_Wr1T);
    cudaGetSymbolAddress((void**)&mlt,  g_MlT);
    cudaGetSymbolAddress((void**)&mrt,  g_MrT);
    cudaGetSymbolAddress((void**)&wo2t, g_Wo2T);

    cudaFuncSetAttribute(mlp_kernel,      cudaFuncAttributeMaxDynamicSharedMemorySize, MLP_SMEM_BYTES);
    cudaFuncSetAttribute(out_gemm_kernel, cudaFuncAttributeMaxDynamicSharedMemorySize, F_SMEM_BYTES);

    // One-time side stream + events (created outside capture on the first
    // call; reused on every subsequent call — no device memory involved).
    static cudaStream_t s2 = nullptr;
    static cudaEvent_t evFork = nullptr, evJoin = nullptr;
    if (!s2) {
        cudaStreamCreateWithFlags(&s2, cudaStreamNonBlocking);
        cudaEventCreateWithFlags(&evFork, cudaEventDisableTiming);
        cudaEventCreateWithFlags(&evJoin, cudaEventDisableTiming);
    }

    const int gridL = (nL + 63) / 64;
    const int gridR = (nR + 63) / 64;
    const int gridO = (nO + 63) / 64;

    const uint4* wl1h = (const uint4*)wl1t;
    const uint4* wl1l = (const uint4*)(wl1t + EMB * 64);
    const uint4* wr1h = (const uint4*)wr1t;
    const uint4* wr1l = (const uint4*)(wr1t + EMB * 64);
    const uint4* mlh  = (const uint4*)mlt;
    const uint4* mll  = (const uint4*)(mlt + EMB * EMB);
    const uint4* mrh  = (const uint4*)mrt;
    const uint4* mrl  = (const uint4*)(mrt + EMB * EMB);
    const uint4* wo2h = (const uint4*)wo2t;
    const uint4* wo2l = (const uint4*)(wo2t + EMB * EMB);

    // 0) zero the conv accumulator
    cudaMemsetAsync(gConv, 0, (size_t)nR * EMB * sizeof(float));
    // 1) weight fold + transpose/split
    fuse_wb_kernel<<<dim3(EMB + 1, 2), EMB>>>(Wl2, Wr2, bl2, br2, Wo1, gMl, gMr, gcl, gcr);
    prep_weights_kernel<<<5, EMB>>>(Wl1, Wr1, gMl, gMr, Wo2, wl1t, wr1t, mlt, mrt, wo2t);
    // 2) left MLP: L = relu(left@Wl1 + bl1) @ Ml + cl
    mlp_kernel<<<gridL, 256, MLP_SMEM_BYTES>>>(left, wl1h, wl1l, bl1,
                                               mlh, mll, gcl, gL, nL);
    // 3) FORK: scatter (needs only L + zeroed conv) runs on s2 concurrently
    //    with the right MLP on the main stream.
    cudaEventRecord(evFork, 0);
    cudaStreamWaitEvent(s2, evFork, 0);
    scatter_kernel<<<(E + 7) / 8, 256, 0, s2>>>(eidx, ew, gL, gConv, E);
    mlp_kernel<<<gridR, 256, MLP_SMEM_BYTES>>>(right, wr1h, wr1l, nullptr,
                                               mrh, mrl, gcr, gS, nR);
    // 4) JOIN, then output GEMM: out = relu(S + conv + bo1) @ Wo2 + bo2
    cudaEventRecord(evJoin, s2);
    cudaStreamWaitEvent(0, evJoin, 0);
    out_gemm_kernel<<<gridO, 256, F_SMEM_BYTES>>>(gS, gConv, wo2h, wo2l,
                                                  bo1, bo2, (float*)d_out, nO);
}

// round 11
// speedup vs baseline: 1.2973x; 1.2973x over previous
#include <cuda_runtime.h>
#include <cuda_bf16.h>
#include <cstdint>

// Problem constants (fixed by the dataset)
#define N_LEFT   100000
#define N_RIGHT  100000
#define N_EDGES  600000
#define EMB      128

// ---------------------------------------------------------------------------
// Device scratch (allocation-free rule: __device__ globals)
// ---------------------------------------------------------------------------
__device__ float g_L [N_LEFT  * EMB];   // transformed left (scatter source)
__device__ float g_S [N_RIGHT * EMB];   // transformed right + conv accumulator
__device__ float g_Ml[EMB * EMB];       // Wl2 @ Wo1[0:128]
__device__ float g_Mr[EMB * EMB];       // Wr2 @ Wo1[128:256]
__device__ float g_cl[EMB];
__device__ float g_cr[EMB];

// Pre-transposed bf16 hi/lo weight images, [n][k] k-contiguous (B^T layout).
__device__ __align__(16) __nv_bfloat16 g_Wl1T[2][EMB * 64];
__device__ __align__(16) __nv_bfloat16 g_Wr1T[2][EMB * 64];
__device__ __align__(16) __nv_bfloat16 g_MlT [2][EMB * EMB];
__device__ __align__(16) __nv_bfloat16 g_MrT [2][EMB * EMB];
__device__ __align__(16) __nv_bfloat16 g_Wo2T[2][EMB * EMB];

// ---------------------------------------------------------------------------
// PTX helpers (all baseline sm_80+)
// ---------------------------------------------------------------------------
__device__ __forceinline__ void mma16816(float* d, const uint32_t* a, const uint32_t* b) {
    asm volatile(
        "mma.sync.aligned.m16n8k16.row.col.f32.bf16.bf16.f32 "
        "{%0,%1,%2,%3}, {%4,%5,%6,%7}, {%8,%9}, {%0,%1,%2,%3};"
        : "+f"(d[0]), "+f"(d[1]), "+f"(d[2]), "+f"(d[3])
        : "r"(a[0]), "r"(a[1]), "r"(a[2]), "r"(a[3]), "r"(b[0]), "r"(b[1]));
}
__device__ __forceinline__ void ldsm_x4(uint32_t& r0, uint32_t& r1, uint32_t& r2, uint32_t& r3,
                                        uint32_t addr) {
    asm volatile("ldmatrix.sync.aligned.m8n8.x4.shared.b16 {%0,%1,%2,%3}, [%4];"
                 : "=r"(r0), "=r"(r1), "=r"(r2), "=r"(r3) : "r"(addr));
}
__device__ __forceinline__ uint32_t cvta_s(const void* p) {
    return (uint32_t)__cvta_generic_to_shared(p);
}
__device__ __forceinline__ void cp_async16(uint32_t dst, const void* src) {
    asm volatile("cp.async.cg.shared.global [%0], [%1], 16;" :: "r"(dst), "l"(src));
}
__device__ __forceinline__ void cp_commit() {
    asm volatile("cp.async.commit_group;");
}
__device__ __forceinline__ void cp_wait0() {
    asm volatile("cp.async.wait_group 0;");
}

// ---------------------------------------------------------------------------
// MMA stage: acc[MT][4][4] += split3( A[MT*32][K] @ B[128][K]^T )
// smem row stride K+8 (16B-aligned rows, conflict-free ldmatrix).
// ---------------------------------------------------------------------------
template<int K, int MT>
__device__ __forceinline__ void mma_stage(const __nv_bfloat16* __restrict__ Ahi,
                                          const __nv_bfloat16* __restrict__ Alo,
                                          const __nv_bfloat16* __restrict__ Bhi,
                                          const __nv_bfloat16* __restrict__ Blo,
                                          float acc[][4][4],
                                          int warp_m, int warp_n, int lane)
{
    constexpr int SK = K + 8;
    const int tr = lane & 7, quad = lane >> 3;
    const int a_row = warp_m * (MT * 16) + tr + (quad & 1) * 8;
    const int a_col = (quad >> 1) * 8;
    const int b_row = warp_n * 32 + tr + (quad >> 1) * 8;
    const int b_col = (quad & 1) * 8;

    uint32_t aAh = cvta_s(Ahi) + (uint32_t)(a_row * SK + a_col) * 2;
    uint32_t aAl = cvta_s(Alo) + (uint32_t)(a_row * SK + a_col) * 2;
    uint32_t aBh = cvta_s(Bhi) + (uint32_t)(b_row * SK + b_col) * 2;
    uint32_t aBl = cvta_s(Blo) + (uint32_t)(b_row * SK + b_col) * 2;

#pragma unroll
    for (int kc = 0; kc < K / 16; kc++) {
        const uint32_t ko = kc * 32;   // 16 elems = 32 bytes
        uint32_t ah[MT][4], al[MT][4], bh[2][4], bl[2][4];
#pragma unroll
        for (int mt = 0; mt < MT; mt++) {
            const uint32_t mo = (uint32_t)(mt * 16 * SK) * 2 + ko;
            ldsm_x4(ah[mt][0], ah[mt][1], ah[mt][2], ah[mt][3], aAh + mo);
            ldsm_x4(al[mt][0], al[mt][1], al[mt][2], al[mt][3], aAl + mo);
        }
#pragma unroll
        for (int np = 0; np < 2; np++) {
            const uint32_t no = (uint32_t)(np * 16 * SK) * 2 + ko;
            ldsm_x4(bh[np][0], bh[np][1], bh[np][2], bh[np][3], aBh + no);
            ldsm_x4(bl[np][0], bl[np][1], bl[np][2], bl[np][3], aBl + no);
        }
#pragma unroll
        for (int mt = 0; mt < MT; mt++)
#pragma unroll
            for (int nt = 0; nt < 4; nt++) {
                const uint32_t* ph = &bh[nt >> 1][(nt & 1) * 2];
                const uint32_t* pl = &bl[nt >> 1][(nt & 1) * 2];
                mma16816(acc[mt][nt], ah[mt], ph);
                mma16816(acc[mt][nt], ah[mt], pl);
                mma16816(acc[mt][nt], al[mt], ph);
            }
    }
}

// Async copy a [128][K] bf16 image from gmem (packed) into padded smem.
template<int K>
__device__ __forceinline__ void load_B_async(__nv_bfloat16* __restrict__ dst,
                                             const uint4* __restrict__ src, int tid)
{
    constexpr int SK = K + 8;
    constexpr int NV = 128 * K / 8;
#pragma unroll
    for (int i = tid; i < NV; i += 256) {
        const int row = i / (K / 8);
        const int col = (i % (K / 8)) * 8;
        cp_async16(cvta_s(dst + row * SK + col), src + i);
    }
}

// bf16 hi/lo split + smem store helper (2 packed pairs from a float4)
__device__ __forceinline__ void split_store4(__nv_bfloat16* hi, __nv_bfloat16* lo,
                                             int idx, float4 v)
{
    __nv_bfloat16 hx = __float2bfloat16(v.x), hy = __float2bfloat16(v.y);
    __nv_bfloat16 hz = __float2bfloat16(v.z), hw = __float2bfloat16(v.w);
    __nv_bfloat162 h0(hx, hy), h1(hz, hw);
    __nv_bfloat162 l0(__float2bfloat16(v.x - __bfloat162float(hx)),
                      __float2bfloat16(v.y - __bfloat162float(hy)));
    __nv_bfloat162 l1(__float2bfloat16(v.z - __bfloat162float(hz)),
                      __float2bfloat16(v.w - __bfloat162float(hw)));
    *(uint32_t*)(hi + idx)     = *(uint32_t*)&h0;
    *(uint32_t*)(hi + idx + 2) = *(uint32_t*)&h1;
    *(uint32_t*)(lo + idx)     = *(uint32_t*)&l0;
    *(uint32_t*)(lo + idx + 2) = *(uint32_t*)&l1;
}

// Load A[row0..+63][0..K) fp32 from gmem, bf16 hi/lo split, padded smem.
template<int K>
__device__ __forceinline__ void load_A64(__nv_bfloat16* __restrict__ hi,
                                         __nv_bfloat16* __restrict__ lo,
                                         const float* __restrict__ X,
                                         int row0, int M, int tid)
{
    constexpr int SK = K + 8;
    const int row  = tid >> 2;
    const int grow = row0 + row;
    const bool valid = grow < M;
    const float* xr = X + (size_t)grow * K;
    const int cbase = (tid & 3) * (K / 4);
#pragma unroll
    for (int q = 0; q < K / 16; q++) {
        const int c0 = cbase + q * 4;
        float4 v = valid ? *(const float4*)(xr + c0) : make_float4(0.f, 0.f, 0.f, 0.f);
        split_store4(hi, lo, row * SK + c0, v);
    }
}

// ---------------------------------------------------------------------------
// MERGED fused 2-layer MLP (left + right in one launch), M=64 per CTA,
// overlaid smem (2 CTAs/SM):  C = relu(X @ W1 [+ b1]) @ W2 + b2
// blockIdx.x < gridL -> left side; else right side.
// ---------------------------------------------------------------------------
#define K1 64
#define K2 128
#define SK1 (K1 + 8)
#define SK2 (K2 + 8)
#define M_B1H 0
#define M_B1L (128 * SK1)                   // 9216
#define M_A1H (2 * 128 * SK1)               // 18432
#define M_A1L (M_A1H + 64 * SK1)            // 23040
#define M_HH  0
#define M_HL  (64 * SK2)                    // 8704
#define M_B2H 18432
#define M_B2L (M_B2H + 128 * SK2)           // 35840
#define MLP_SMEM_ELEMS (M_B2L + 128 * SK2)  // 53248
#define MLP_SMEM_BYTES (MLP_SMEM_ELEMS * 2) // 106496

__global__ void __launch_bounds__(256, 2)
mlp2_kernel(const float* __restrict__ XL, const float* __restrict__ XR,
            const uint4* __restrict__ L_B1hi, const uint4* __restrict__ L_B1lo,
            const uint4* __restrict__ R_B1hi, const uint4* __restrict__ R_B1lo,
            const float* __restrict__ bl1,          // left stage-1 bias (right has none)
            const uint4* __restrict__ L_B2hi, const uint4* __restrict__ L_B2lo,
            const uint4* __restrict__ R_B2hi, const uint4* __restrict__ R_B2lo,
            const float* __restrict__ cl, const float* __restrict__ cr,
            float* __restrict__ CL, float* __restrict__ CR,
            int nL, int nR, int gridL)
{
    extern __shared__ __nv_bfloat16 sm[];
    const int tid = threadIdx.x;
    const int wid = tid >> 5, lane = tid & 31;
    const int warp_m = wid >> 2, warp_n = wid & 3;
    const int g = lane >> 2, c = lane & 3;

    const bool leftSide = (blockIdx.x < gridL);
    const int  bidx  = leftSide ? blockIdx.x : blockIdx.x - gridL;
    const int  row0  = bidx * 64;
    const int  M     = leftSide ? nL : nR;
    const float* X   = leftSide ? XL : XR;
    const uint4* B1hi = leftSide ? L_B1hi : R_B1hi;
    const uint4* B1lo = leftSide ? L_B1lo : R_B1lo;
    const uint4* B2hi = leftSide ? L_B2hi : R_B2hi;
    const uint4* B2lo = leftSide ? L_B2lo : R_B2lo;
    const float* bias1 = leftSide ? bl1 : nullptr;
    const float* bias2 = leftSide ? cl : cr;
    float* C          = leftSide ? CL : CR;

    load_B_async<K1>(sm + M_B1H, B1hi, tid);
    load_B_async<K1>(sm + M_B1L, B1lo, tid);
    cp_commit();
    load_A64<K1>(sm + M_A1H, sm + M_A1L, X, row0, M, tid);  // overlaps B1 fetch
    cp_wait0();
    __syncthreads();

    float acc[2][4][4];
#pragma unroll
    for (int mt = 0; mt < 2; mt++)
#pragma unroll
        for (int nt = 0; nt < 4; nt++)
#pragma unroll
            for (int j = 0; j < 4; j++) acc[mt][nt][j] = 0.f;

    mma_stage<K1, 2>(sm + M_A1H, sm + M_A1L, sm + M_B1H, sm + M_B1L,
                     acc, warp_m, warp_n, lane);
    __syncthreads();   // all warps done reading A1/B1

    // prefetch B2 over A1/X region (A1 fully consumed), overlapping epilogue-1
    load_B_async<K2>(sm + M_B2H, B2hi, tid);
    load_B_async<K2>(sm + M_B2L, B2lo, tid);
    cp_commit();

    // epilogue 1: H = relu(acc + b1) -> bf16 hi/lo over B1 region
#pragma unroll
    for (int mt = 0; mt < 2; mt++) {
        const int row = warp_m * 32 + mt * 16 + g;
#pragma unroll
        for (int nt = 0; nt < 4; nt++) {
            const int col = warp_n * 32 + nt * 8 + c * 2;
            float v0 = acc[mt][nt][0], v1 = acc[mt][nt][1];
            float v2 = acc[mt][nt][2], v3 = acc[mt][nt][3];
            if (bias1) {
                float2 b = *(const float2*)(bias1 + col);
                v0 += b.x; v1 += b.y; v2 += b.x; v3 += b.y;
            }
            v0 = fmaxf(v0, 0.f); v1 = fmaxf(v1, 0.f);
            v2 = fmaxf(v2, 0.f); v3 = fmaxf(v3, 0.f);
            __nv_bfloat16 h0 = __float2bfloat16(v0), h1 = __float2bfloat16(v1);
            __nv_bfloat16 h2 = __float2bfloat16(v2), h3 = __float2bfloat16(v3);
            __nv_bfloat162 hp0(h0, h1), hp1(h2, h3);
            __nv_bfloat162 lp0(__float2bfloat16(v0 - __bfloat162float(h0)),
                               __float2bfloat16(v1 - __bfloat162float(h1)));
            __nv_bfloat162 lp1(__float2bfloat16(v2 - __bfloat162float(h2)),
                               __float2bfloat16(v3 - __bfloat162float(h3)));
            *(uint32_t*)(sm + M_HH + row * SK2 + col)       = *(uint32_t*)&hp0;
            *(uint32_t*)(sm + M_HH + (row + 8) * SK2 + col) = *(uint32_t*)&hp1;
            *(uint32_t*)(sm + M_HL + row * SK2 + col)       = *(uint32_t*)&lp0;
            *(uint32_t*)(sm + M_HL + (row + 8) * SK2 + col) = *(uint32_t*)&lp1;
        }
    }
    cp_wait0();
    __syncthreads();

#pragma unroll
    for (int mt = 0; mt < 2; mt++)
#pragma unroll
        for (int nt = 0; nt < 4; nt++)
#pragma unroll
            for (int j = 0; j < 4; j++) acc[mt][nt][j] = 0.f;

    mma_stage<K2, 2>(sm + M_HH, sm + M_HL, sm + M_B2H, sm + M_B2L,
                     acc, warp_m, warp_n, lane);

#pragma unroll
    for (int mt = 0; mt < 2; mt++) {
        const int r = row0 + warp_m * 32 + mt * 16 + g;
#pragma unroll
        for (int nt = 0; nt < 4; nt++) {
            const int col = warp_n * 32 + nt * 8 + c * 2;
            float2 b = *(const float2*)(bias2 + col);
            if (r < M) {
                float2 o0 = make_float2(acc[mt][nt][0] + b.x, acc[mt][nt][1] + b.y);
                *(float2*)(C + (size_t)r * EMB + col) = o0;
            }
            if (r + 8 < M) {
                float2 o1 = make_float2(acc[mt][nt][2] + b.x, acc[mt][nt][3] + b.y);
                *(float2*)(C + (size_t)(r + 8) * EMB + col) = o1;
            }
        }
    }
}

// ---------------------------------------------------------------------------
// Edge scatter: one warp per edge.  S[dst] += w_e * L[src]  (red.global.v4)
// ---------------------------------------------------------------------------
__global__ void scatter_kernel(const int* __restrict__ eidx,
                               const float* __restrict__ ew,
                               const float* __restrict__ L,
                               float* __restrict__ S,
                               int E)
{
    const int warp = (blockIdx.x * blockDim.x + threadIdx.x) >> 5;
    const int lane = threadIdx.x & 31;
    if (warp >= E) return;

    const int src = eidx[warp];
    const int dst = eidx[E + warp];
    const float w = ew[warp];

    float4 v = *(const float4*)(L + (size_t)src * EMB + lane * 4);
    float* out = S + (size_t)dst * EMB + lane * 4;
    asm volatile("red.global.add.v4.f32 [%0], {%1, %2, %3, %4};"
                 :: "l"(out), "f"(w * v.x), "f"(w * v.y), "f"(w * v.z), "f"(w * v.w)
                 : "memory");
}

// ---------------------------------------------------------------------------
// Output GEMM, M=64 per CTA (2 CTAs/SM):  out = relu(S + bo1) @ Wo2 + bo2
// ---------------------------------------------------------------------------
#define F_AH 0
#define F_AL (64 * SK2)                  // 8704
#define F_BH (2 * 64 * SK2)              // 17408
#define F_BL (F_BH + 128 * SK2)          // 34816
#define F_SMEM_ELEMS (F_BL + 128 * SK2)  // 52224
#define F_SMEM_BYTES (F_SMEM_ELEMS * 2)  // 104448

__global__ void __launch_bounds__(256, 2)
out_gemm_kernel(const float* __restrict__ S,
                const uint4* __restrict__ Bhi, const uint4* __restrict__ Blo,
                const float* __restrict__ bo1,
                const float* __restrict__ bo2,
                float* __restrict__ C, int M)
{
    extern __shared__ __nv_bfloat16 sm[];
    const int tid = threadIdx.x;
    const int wid = tid >> 5, lane = tid & 31;
    const int warp_m = wid >> 2, warp_n = wid & 3;
    const int g = lane >> 2, c = lane & 3;
    const int row0 = blockIdx.x * 64;

    load_B_async<K2>(sm + F_BH, Bhi, tid);
    load_B_async<K2>(sm + F_BL, Blo, tid);
    cp_commit();

    // A-load: relu(S + bo1), split, store (overlaps B fetch)
    {
        const int row  = tid >> 2;
        const int grow = row0 + row;
        const bool valid = grow < M;
        const float* sr = S + (size_t)grow * K2;
        const int cbase = (tid & 3) * (K2 / 4);
#pragma unroll
        for (int q = 0; q < K2 / 16; q++) {
            const int c0 = cbase + q * 4;
            float4 v = make_float4(0.f, 0.f, 0.f, 0.f);
            if (valid) {
                float4 a = *(const float4*)(sr + c0);
                float4 pb = *(const float4*)(bo1 + c0);
                v.x = fmaxf(a.x + pb.x, 0.f);
                v.y = fmaxf(a.y + pb.y, 0.f);
                v.z = fmaxf(a.z + pb.z, 0.f);
                v.w = fmaxf(a.w + pb.w, 0.f);
            }
            split_store4(sm + F_AH, sm + F_AL, row * SK2 + c0, v);
        }
    }
    cp_wait0();
    __syncthreads();

    float acc[2][4][4];
#pragma unroll
    for (int mt = 0; mt < 2; mt++)
#pragma unroll
        for (int nt = 0; nt < 4; nt++)
#pragma unroll
            for (int j = 0; j < 4; j++) acc[mt][nt][j] = 0.f;

    mma_stage<K2, 2>(sm + F_AH, sm + F_AL, sm + F_BH, sm + F_BL,
                     acc, warp_m, warp_n, lane);

#pragma unroll
    for (int mt = 0; mt < 2; mt++) {
        const int r = row0 + warp_m * 32 + mt * 16 + g;
#pragma unroll
        for (int nt = 0; nt < 4; nt++) {
            const int col = warp_n * 32 + nt * 8 + c * 2;
            float2 b = *(const float2*)(bo2 + col);
            if (r < M) {
                float2 o0 = make_float2(acc[mt][nt][0] + b.x, acc[mt][nt][1] + b.y);
                *(float2*)(C + (size_t)r * EMB + col) = o0;
            }
            if (r + 8 < M) {
                float2 o1 = make_float2(acc[mt][nt][2] + b.x, acc[mt][nt][3] + b.y);
                *(float2*)(C + (size_t)(r + 8) * EMB + col) = o1;
            }
        }
    }
}

// ---------------------------------------------------------------------------
// Weight fusion (matrix rows 0..127, bias row 128)
// ---------------------------------------------------------------------------
__global__ void fuse_wb_kernel(const float* __restrict__ Wl2,
                               const float* __restrict__ Wr2,
                               const float* __restrict__ bl2,
                               const float* __restrict__ br2,
                               const float* __restrict__ Wo1,
                               float* __restrict__ Ml, float* __restrict__ Mr,
                               float* __restrict__ cl, float* __restrict__ cr)
{
    const int i = blockIdx.x, j = threadIdx.x;
    const bool rs = (blockIdx.y != 0);
    const int off = rs ? EMB : 0;
    const float* vec = (i < EMB) ? ((rs ? Wr2 : Wl2) + i * EMB) : (rs ? br2 : bl2);
    float s = 0.f;
#pragma unroll 8
    for (int k = 0; k < EMB; k++)
        s += vec[k] * Wo1[(off + k) * EMB + j];
    if (i < EMB) (rs ? Mr : Ml)[i * EMB + j] = s;
    else         (rs ? cr : cl)[j] = s;
}

// ---------------------------------------------------------------------------
// Prep: element-parallel transpose + bf16 hi/lo split of the 5 weight mats.
// One thread per element; fully latency-hidden (was a serial K-loop before).
// Segment map (element counts): Wl1 8192 | Wr1 8192 | Ml 16384 | Mr 16384 | Wo2 16384
// ---------------------------------------------------------------------------
__global__ void prep_weights_kernel(const float* __restrict__ Wl1,
                                    const float* __restrict__ Wr1,
                                    const float* __restrict__ Ml,
                                    const float* __restrict__ Mr,
                                    const float* __restrict__ Wo2,
                                    __nv_bfloat16* __restrict__ Wl1T,
                                    __nv_bfloat16* __restrict__ Wr1T,
                                    __nv_bfloat16* __restrict__ MlT,
                                    __nv_bfloat16* __restrict__ MrT,
                                    __nv_bfloat16* __restrict__ Wo2T)
{
    const int idx = blockIdx.x * 256 + threadIdx.x;   // 0 .. 65535
    const float* W; __nv_bfloat16* T; int local, logK;
    if (idx < 8192)        { W = Wl1; T = Wl1T; local = idx;         logK = 6; }
    else if (idx < 16384)  { W = Wr1; T = Wr1T; local = idx - 8192;  logK = 6; }
    else if (idx < 32768)  { W = Ml;  T = MlT;  local = idx - 16384; logK = 7; }
    else if (idx < 49152)  { W = Mr;  T = MrT;  local = idx - 32768; logK = 7; }
    else                   { W = Wo2; T = Wo2T; local = idx - 49152; logK = 7; }
    const int K = 1 << logK;
    const int n = local >> logK;          // output row (k-contiguous image)
    const int k = local & (K - 1);
    const float w = W[k * EMB + n];
    const __nv_bfloat16 h = __float2bfloat16(w);
    const __nv_bfloat16 l = __float2bfloat16(w - __bfloat162float(h));
    T[n * K + k]           = h;           // hi image
    T[EMB * K + n * K + k] = l;           // lo image follows hi
}

// ---------------------------------------------------------------------------
// Launch
// ---------------------------------------------------------------------------
extern "C" void kernel_launch(void* const* d_in, const int* in_sizes, int n_in,
                              void* d_out, int out_size)
{
    const float* left  = (const float*)d_in[0];
    const int*   eidx  = (const int*)  d_in[1];
    const float* ew    = (const float*)d_in[2];
    const float* right = (const float*)d_in[3];
    const float* Wl1 = (const float*)d_in[5];
    const float* bl1 = (const float*)d_in[6];
    const float* Wl2 = (const float*)d_in[7];
    const float* bl2 = (const float*)d_in[8];
    const float* Wr1 = (const float*)d_in[9];
    const float* Wr2 = (const float*)d_in[10];
    const float* br2 = (const float*)d_in[11];
    const float* Wo1 = (const float*)d_in[12];
    const float* bo1 = (const float*)d_in[13];
    const float* Wo2 = (const float*)d_in[14];
    const float* bo2 = (const float*)d_in[15];

    const int nL = in_sizes[0] / 64;
    const int E  = in_sizes[1] / 2;
    const int nR = in_sizes[3] / 64;
    const int nO = out_size / EMB;

    float *gL, *gS, *gMl, *gMr, *gcl, *gcr;
    cudaGetSymbolAddress((void**)&gL,  g_L);
    cudaGetSymbolAddress((void**)&gS,  g_S);
    cudaGetSymbolAddress((void**)&gMl, g_Ml);
    cudaGetSymbolAddress((void**)&gMr, g_Mr);
    cudaGetSymbolAddress((void**)&gcl, g_cl);
    cudaGetSymbolAddress((void**)&gcr, g_cr);

    __nv_bfloat16 *wl1t, *wr1t, *mlt, *mrt, *wo2t;
    cudaGetSymbolAddress((void**)&wl1t, g_Wl1T);
    cudaGetSymbolAddress((void**)&wr1t, g_Wr1T);
    cudaGetSymbolAddress((void**)&mlt,  g_MlT);
    cudaGetSymbolAddress((void**)&mrt,  g_MrT);
    cudaGetSymbolAddress((void**)&wo2t, g_Wo2T);

    cudaFuncSetAttribute(mlp2_kernel,     cudaFuncAttributeMaxDynamicSharedMemorySize, MLP_SMEM_BYTES);
    cudaFuncSetAttribute(out_gemm_kernel, cudaFuncAttributeMaxDynamicSharedMemorySize, F_SMEM_BYTES);

    const int gridL = (nL + 63) / 64;
    const int gridR = (nR + 63) / 64;
    const int gridO = (nO + 63) / 64;

    const uint4* wl1h = (const uint4*)wl1t;
    const uint4* wl1l = (const uint4*)(wl1t + EMB * 64);
    const uint4* wr1h = (const uint4*)wr1t;
    const uint4* wr1l = (const uint4*)(wr1t + EMB * 64);
    const uint4* mlh  = (const uint4*)mlt;
    const uint4* mll  = (const uint4*)(mlt + EMB * EMB);
    const uint4* mrh  = (const uint4*)mrt;
    const uint4* mrl  = (const uint4*)(mrt + EMB * EMB);
    const uint4* wo2h = (const uint4*)wo2t;
    const uint4* wo2l = (const uint4*)(wo2t + EMB * EMB);

    // 1) fold Wl2@Wo1a / Wr2@Wo1b (+ bias rows), then transpose+split to bf16
    fuse_wb_kernel<<<dim3(EMB + 1, 2), EMB>>>(Wl2, Wr2, bl2, br2, Wo1, gMl, gMr, gcl, gcr);
    prep_weights_kernel<<<256, 256>>>(Wl1, Wr1, gMl, gMr, Wo2, wl1t, wr1t, mlt, mrt, wo2t);
    // 2) merged MLP: L = relu(left@Wl1+bl1)@Ml+cl ; S = relu(right@Wr1)@Mr+cr
    mlp2_kernel<<<gridL + gridR, 256, MLP_SMEM_BYTES>>>(
        left, right,
        wl1h, wl1l, wr1h, wr1l, bl1,
        mlh, mll, mrh, mrl, gcl, gcr,
        gL, gS, nL, nR, gridL);
    // 3) S[dst] += e * L[src]   (edge-parallel vector reductions)
    scatter_kernel<<<(E + 7) / 8, 256>>>(eidx, ew, gL, gS, E);
    // 4) out = relu(S + bo1) @ Wo2 + bo2
    out_gemm_kernel<<<gridO, 256, F_SMEM_BYTES>>>(gS, wo2h, wo2l, bo1, bo2, (float*)d_out, nO);
}

// round 12
// speedup vs baseline: 1.3094x; 1.0093x over previous
#include <cuda_runtime.h>
#include <cuda_bf16.h>
#include <cstdint>

// Problem constants (fixed by the dataset)
#define N_LEFT   100000
#define N_RIGHT  100000
#define N_EDGES  600000
#define EMB      128

// ---------------------------------------------------------------------------
// Device scratch (allocation-free rule: __device__ globals)
// ---------------------------------------------------------------------------
__device__ float g_L [N_LEFT  * EMB];   // transformed left (scatter source)
__device__ float g_S [N_RIGHT * EMB];   // transformed right + conv accumulator
__device__ float g_Ml[EMB * EMB];       // Wl2 @ Wo1[0:128]
__device__ float g_Mr[EMB * EMB];       // Wr2 @ Wo1[128:256]
__device__ float g_cl[EMB];
__device__ float g_cr[EMB];

// Pre-transposed tf32-rounded fp32 weight images, [n][k] k-contiguous (B^T).
__device__ __align__(16) float g_Wl1T[EMB * 64];
__device__ __align__(16) float g_Wr1T[EMB * 64];
__device__ __align__(16) float g_MlT [EMB * EMB];
__device__ __align__(16) float g_MrT [EMB * EMB];
__device__ __align__(16) float g_Wo2T[EMB * EMB];

// ---------------------------------------------------------------------------
// PTX helpers (all baseline sm_80+)
// ---------------------------------------------------------------------------
__device__ __forceinline__ void mma16808(float* d, const uint32_t* a, const uint32_t* b) {
    asm volatile(
        "mma.sync.aligned.m16n8k8.row.col.f32.tf32.tf32.f32 "
        "{%0,%1,%2,%3}, {%4,%5,%6,%7}, {%8,%9}, {%0,%1,%2,%3};"
        : "+f"(d[0]), "+f"(d[1]), "+f"(d[2]), "+f"(d[3])
        : "r"(a[0]), "r"(a[1]), "r"(a[2]), "r"(a[3]), "r"(b[0]), "r"(b[1]));
}
__device__ __forceinline__ void ldsm_x4(uint32_t& r0, uint32_t& r1, uint32_t& r2, uint32_t& r3,
                                        uint32_t addr) {
    asm volatile("ldmatrix.sync.aligned.m8n8.x4.shared.b16 {%0,%1,%2,%3}, [%4];"
                 : "=r"(r0), "=r"(r1), "=r"(r2), "=r"(r3) : "r"(addr));
}
__device__ __forceinline__ uint32_t cvta_s(const void* p) {
    return (uint32_t)__cvta_generic_to_shared(p);
}
__device__ __forceinline__ void cp_async16(uint32_t dst, const void* src) {
    asm volatile("cp.async.cg.shared.global [%0], [%1], 16;" :: "r"(dst), "l"(src));
}
__device__ __forceinline__ void cp_commit() {
    asm volatile("cp.async.commit_group;");
}
__device__ __forceinline__ void cp_wait0() {
    asm volatile("cp.async.wait_group 0;");
}
__device__ __forceinline__ float tf32r(float x) {
    uint32_t o;
    asm("cvt.rna.tf32.f32 %0, %1;" : "=r"(o) : "f"(x));
    return __uint_as_float(o);
}

// ---------------------------------------------------------------------------
// tf32 MMA stage: acc[MT][4][4] += A[MT*32][K] @ B[128][K]^T  (single pass)
// A, B fp32 (tf32-rounded) in smem, row stride K+4 floats (16B pad:
// row stride bytes ≡ 16 mod 128 -> conflict-free 16B-chunk ldmatrix).
//
// Fragments per k8 step:
//   A (16 rows x 8 k): ldmatrix.x4 lanes: 0-7 rows+0/k0-3, 8-15 rows+8/k0-3,
//     16-23 rows+0/k4-7, 24-31 rows+8/k4-7  -> regs = a0,a1,a2,a3 exactly.
//   B (16 n x 8 k): ldmatrix.x4 lanes: 0-7 n+0/k0-3, 8-15 n+0/k4-7,
//     16-23 n+8/k0-3, 24-31 n+8/k4-7 -> regs = (b0,b1) of n-tile0, (b0,b1) of n-tile1.
// ---------------------------------------------------------------------------
template<int K, int MT>
__device__ __forceinline__ void mma_stage(const float* __restrict__ A,
                                          const float* __restrict__ B,
                                          float acc[][4][4],
                                          int warp_m, int warp_n, int lane)
{
    constexpr int SK = K + 4;            // floats per row
    const int l7 = lane & 7;
    const int a_row = warp_m * (MT * 16) + l7 + ((lane >> 3) & 1) * 8;
    const uint32_t a_kb = (uint32_t)(lane >> 4) * 16;         // 0 or 16 bytes
    const int b_row = warp_n * 32 + l7 + (lane >> 4) * 8;
    const uint32_t b_kb = (uint32_t)((lane >> 3) & 1) * 16;

    uint32_t aA = cvta_s(A) + (uint32_t)(a_row * SK) * 4 + a_kb;
    uint32_t aB = cvta_s(B) + (uint32_t)(b_row * SK) * 4 + b_kb;

#pragma unroll
    for (int kc = 0; kc < K / 8; kc++) {
        const uint32_t ko = kc * 32;     // 8 tf32 = 32 bytes
        uint32_t a[MT][4], b[2][4];
#pragma unroll
        for (int mt = 0; mt < MT; mt++)
            ldsm_x4(a[mt][0], a[mt][1], a[mt][2], a[mt][3],
                    aA + (uint32_t)(mt * 16 * SK) * 4 + ko);
#pragma unroll
        for (int np = 0; np < 2; np++)
            ldsm_x4(b[np][0], b[np][1], b[np][2], b[np][3],
                    aB + (uint32_t)(np * 16 * SK) * 4 + ko);
#pragma unroll
        for (int mt = 0; mt < MT; mt++)
#pragma unroll
            for (int nt = 0; nt < 4; nt++)
                mma16808(acc[mt][nt], a[mt], &b[nt >> 1][(nt & 1) * 2]);
    }
}

// Async copy a [128][K] fp32 image from gmem (packed) into padded smem.
template<int K>
__device__ __forceinline__ void load_B_async(float* __restrict__ dst,
                                             const uint4* __restrict__ src, int tid)
{
    constexpr int SK = K + 4;
    constexpr int NV = 128 * K / 4;     // uint4 count
#pragma unroll
    for (int i = tid; i < NV; i += 256) {
        const int row = i / (K / 4);
        const int col = (i % (K / 4)) * 4;
        cp_async16(cvta_s(dst + row * SK + col), src + i);
    }
}

// Load A[row0..+63][0..K) fp32 from gmem, tf32-round, store padded smem.
template<int K>
__device__ __forceinline__ void load_A64(float* __restrict__ dst,
                                         const float* __restrict__ X,
                                         int row0, int M, int tid)
{
    constexpr int SK = K + 4;
    const int row  = tid >> 2;
    const int grow = row0 + row;
    const bool valid = grow < M;
    const float* xr = X + (size_t)grow * K;
    const int cbase = (tid & 3) * (K / 4);
#pragma unroll
    for (int q = 0; q < K / 16; q++) {
        const int c0 = cbase + q * 4;
        float4 v = valid ? *(const float4*)(xr + c0) : make_float4(0.f, 0.f, 0.f, 0.f);
        v.x = tf32r(v.x); v.y = tf32r(v.y); v.z = tf32r(v.z); v.w = tf32r(v.w);
        *(float4*)(dst + row * SK + c0) = v;
    }
}

// ---------------------------------------------------------------------------
// MERGED fused 2-layer MLP (left + right in one launch), M=64 per CTA,
// overlaid smem (2 CTAs/SM):  C = relu(X @ W1 [+ b1]) @ W2 + b2
// smem float offsets: B1 [0, 8704) | A1 [8704, 13056)
//   stage2: H over B1 region [0, 8448) | B2 over A1.. [8704, 25600)
// ---------------------------------------------------------------------------
#define K1 64
#define K2 128
#define SK1 (K1 + 4)                    // 68 floats
#define SK2 (K2 + 4)                    // 132 floats
#define ML_B1 0
#define ML_A1 (128 * SK1)               // 8704
#define ML_H  0
#define ML_B2 (128 * SK1)               // 8704 (overlays A1 region)
#define MLP_SMEM_FLOATS (ML_B2 + 128 * SK2)   // 25600
#define MLP_SMEM_BYTES (MLP_SMEM_FLOATS * 4)  // 102400

__global__ void __launch_bounds__(256, 2)
mlp2_kernel(const float* __restrict__ XL, const float* __restrict__ XR,
            const uint4* __restrict__ L_B1, const uint4* __restrict__ R_B1,
            const float* __restrict__ bl1,          // left stage-1 bias (right: none)
            const uint4* __restrict__ L_B2, const uint4* __restrict__ R_B2,
            const float* __restrict__ cl, const float* __restrict__ cr,
            float* __restrict__ CL, float* __restrict__ CR,
            int nL, int nR, int gridL)
{
    extern __shared__ float sm[];
    const int tid = threadIdx.x;
    const int wid = tid >> 5, lane = tid & 31;
    const int warp_m = wid >> 2, warp_n = wid & 3;
    const int g = lane >> 2, c = lane & 3;

    const bool leftSide = (blockIdx.x < gridL);
    const int  bidx  = leftSide ? blockIdx.x : blockIdx.x - gridL;
    const int  row0  = bidx * 64;
    const int  M     = leftSide ? nL : nR;
    const float* X   = leftSide ? XL : XR;
    const uint4* B1  = leftSide ? L_B1 : R_B1;
    const uint4* B2  = leftSide ? L_B2 : R_B2;
    const float* bias1 = leftSide ? bl1 : nullptr;
    const float* bias2 = leftSide ? cl : cr;
    float* C          = leftSide ? CL : CR;

    load_B_async<K1>(sm + ML_B1, B1, tid);
    cp_commit();
    load_A64<K1>(sm + ML_A1, X, row0, M, tid);   // overlaps B1 fetch
    cp_wait0();
    __syncthreads();

    float acc[2][4][4];
#pragma unroll
    for (int mt = 0; mt < 2; mt++)
#pragma unroll
        for (int nt = 0; nt < 4; nt++)
#pragma unroll
            for (int j = 0; j < 4; j++) acc[mt][nt][j] = 0.f;

    mma_stage<K1, 2>(sm + ML_A1, sm + ML_B1, acc, warp_m, warp_n, lane);
    __syncthreads();   // all warps done reading A1/B1

    // prefetch B2 over A1 region (consumed), overlapping epilogue-1
    load_B_async<K2>(sm + ML_B2, B2, tid);
    cp_commit();

    // epilogue 1: H = tf32(relu(acc + b1)) -> fp32 over B1 region
#pragma unroll
    for (int mt = 0; mt < 2; mt++) {
        const int row = warp_m * 32 + mt * 16 + g;
#pragma unroll
        for (int nt = 0; nt < 4; nt++) {
            const int col = warp_n * 32 + nt * 8 + c * 2;
            float v0 = acc[mt][nt][0], v1 = acc[mt][nt][1];
            float v2 = acc[mt][nt][2], v3 = acc[mt][nt][3];
            if (bias1) {
                float2 b = *(const float2*)(bias1 + col);
                v0 += b.x; v1 += b.y; v2 += b.x; v3 += b.y;
            }
            float2 p0 = make_float2(tf32r(fmaxf(v0, 0.f)), tf32r(fmaxf(v1, 0.f)));
            float2 p1 = make_float2(tf32r(fmaxf(v2, 0.f)), tf32r(fmaxf(v3, 0.f)));
            *(float2*)(sm + ML_H + row * SK2 + col)       = p0;
            *(float2*)(sm + ML_H + (row + 8) * SK2 + col) = p1;
        }
    }
    cp_wait0();
    __syncthreads();

#pragma unroll
    for (int mt = 0; mt < 2; mt++)
#pragma unroll
        for (int nt = 0; nt < 4; nt++)
#pragma unroll
            for (int j = 0; j < 4; j++) acc[mt][nt][j] = 0.f;

    mma_stage<K2, 2>(sm + ML_H, sm + ML_B2, acc, warp_m, warp_n, lane);

#pragma unroll
    for (int mt = 0; mt < 2; mt++) {
        const int r = row0 + warp_m * 32 + mt * 16 + g;
#pragma unroll
        for (int nt = 0; nt < 4; nt++) {
            const int col = warp_n * 32 + nt * 8 + c * 2;
            float2 b = *(const float2*)(bias2 + col);
            if (r < M) {
                float2 o0 = make_float2(acc[mt][nt][0] + b.x, acc[mt][nt][1] + b.y);
                *(float2*)(C + (size_t)r * EMB + col) = o0;
            }
            if (r + 8 < M) {
                float2 o1 = make_float2(acc[mt][nt][2] + b.x, acc[mt][nt][3] + b.y);
                *(float2*)(C + (size_t)(r + 8) * EMB + col) = o1;
            }
        }
    }
}

// ---------------------------------------------------------------------------
// Edge scatter: one warp per edge.  S[dst] += w_e * L[src]  (red.global.v4)
// ---------------------------------------------------------------------------
__global__ void scatter_kernel(const int* __restrict__ eidx,
                               const float* __restrict__ ew,
                               const float* __restrict__ L,
                               float* __restrict__ S,
                               int E)
{
    const int warp = (blockIdx.x * blockDim.x + threadIdx.x) >> 5;
    const int lane = threadIdx.x & 31;
    if (warp >= E) return;

    const int src = eidx[warp];
    const int dst = eidx[E + warp];
    const float w = ew[warp];

    float4 v = *(const float4*)(L + (size_t)src * EMB + lane * 4);
    float* out = S + (size_t)dst * EMB + lane * 4;
    asm volatile("red.global.add.v4.f32 [%0], {%1, %2, %3, %4};"
                 :: "l"(out), "f"(w * v.x), "f"(w * v.y), "f"(w * v.z), "f"(w * v.w)
                 : "memory");
}

// ---------------------------------------------------------------------------
// Output GEMM, M=64 per CTA (2 CTAs/SM):  out = relu(S + bo1) @ Wo2 + bo2
// smem float offsets: A [0, 8448) | B [8448, 25344)
// ---------------------------------------------------------------------------
#define F_A 0
#define F_B (64 * SK2)                        // 8448
#define F_SMEM_FLOATS (F_B + 128 * SK2)       // 25344
#define F_SMEM_BYTES (F_SMEM_FLOATS * 4)      // 101376

__global__ void __launch_bounds__(256, 2)
out_gemm_kernel(const float* __restrict__ S,
                const uint4* __restrict__ Bimg,
                const float* __restrict__ bo1,
                const float* __restrict__ bo2,
                float* __restrict__ C, int M)
{
    extern __shared__ float sm[];
    const int tid = threadIdx.x;
    const int wid = tid >> 5, lane = tid & 31;
    const int warp_m = wid >> 2, warp_n = wid & 3;
    const int g = lane >> 2, c = lane & 3;
    const int row0 = blockIdx.x * 64;

    load_B_async<K2>(sm + F_B, Bimg, tid);
    cp_commit();

    // A-load: tf32(relu(S + bo1)), store (overlaps B fetch)
    {
        const int row  = tid >> 2;
        const int grow = row0 + row;
        const bool valid = grow < M;
        const float* sr = S + (size_t)grow * K2;
        const int cbase = (tid & 3) * (K2 / 4);
#pragma unroll
        for (int q = 0; q < K2 / 16; q++) {
            const int c0 = cbase + q * 4;
            float4 v = make_float4(0.f, 0.f, 0.f, 0.f);
            if (valid) {
                float4 a = *(const float4*)(sr + c0);
                float4 pb = *(const float4*)(bo1 + c0);
                v.x = tf32r(fmaxf(a.x + pb.x, 0.f));
                v.y = tf32r(fmaxf(a.y + pb.y, 0.f));
                v.z = tf32r(fmaxf(a.z + pb.z, 0.f));
                v.w = tf32r(fmaxf(a.w + pb.w, 0.f));
            }
            *(float4*)(sm + F_A + row * SK2 + c0) = v;
        }
    }
    cp_wait0();
    __syncthreads();

    float acc[2][4][4];
#pragma unroll
    for (int mt = 0; mt < 2; mt++)
#pragma unroll
        for (int nt = 0; nt < 4; nt++)
#pragma unroll
            for (int j = 0; j < 4; j++) acc[mt][nt][j] = 0.f;

    mma_stage<K2, 2>(sm + F_A, sm + F_B, acc, warp_m, warp_n, lane);

#pragma unroll
    for (int mt = 0; mt < 2; mt++) {
        const int r = row0 + warp_m * 32 + mt * 16 + g;
#pragma unroll
        for (int nt = 0; nt < 4; nt++) {
            const int col = warp_n * 32 + nt * 8 + c * 2;
            float2 b = *(const float2*)(bo2 + col);
            if (r < M) {
                float2 o0 = make_float2(acc[mt][nt][0] + b.x, acc[mt][nt][1] + b.y);
                *(float2*)(C + (size_t)r * EMB + col) = o0;
            }
            if (r + 8 < M) {
                float2 o1 = make_float2(acc[mt][nt][2] + b.x, acc[mt][nt][3] + b.y);
                *(float2*)(C + (size_t)(r + 8) * EMB + col) = o1;
            }
        }
    }
}

// ---------------------------------------------------------------------------
// Weight fusion: two kernels (matrix, then bias) so mlp2 lands at launch idx 3
// ---------------------------------------------------------------------------
__global__ void fuse_w_kernel(const float* __restrict__ Wl2,
                              const float* __restrict__ Wr2,
                              const float* __restrict__ Wo1,
                              float* __restrict__ Ml, float* __restrict__ Mr)
{
    const int i = blockIdx.x, j = threadIdx.x;
    const bool rs = (blockIdx.y != 0);
    const int off = rs ? EMB : 0;
    const float* vec = (rs ? Wr2 : Wl2) + i * EMB;
    float s = 0.f;
#pragma unroll 8
    for (int k = 0; k < EMB; k++)
        s += vec[k] * Wo1[(off + k) * EMB + j];
    (rs ? Mr : Ml)[i * EMB + j] = s;
}

__global__ void fuse_b_kernel(const float* __restrict__ bl2,
                              const float* __restrict__ br2,
                              const float* __restrict__ Wo1,
                              float* __restrict__ cl, float* __restrict__ cr)
{
    const int j = threadIdx.x;
    const bool rs = (blockIdx.x != 0);
    const float* b = rs ? br2 : bl2;
    const int off = rs ? EMB : 0;
    float s = 0.f;
#pragma unroll 8
    for (int k = 0; k < EMB; k++)
        s += b[k] * Wo1[(off + k) * EMB + j];
    (rs ? cr : cl)[j] = s;
}

// ---------------------------------------------------------------------------
// Prep: element-parallel transpose + tf32 rounding of the 5 weight matrices.
// Segments: Wl1 8192 | Wr1 8192 | Ml 16384 | Mr 16384 | Wo2 16384 = 65536
// ---------------------------------------------------------------------------
__global__ void prep_weights_kernel(const float* __restrict__ Wl1,
                                    const float* __restrict__ Wr1,
                                    const float* __restrict__ Ml,
                                    const float* __restrict__ Mr,
                                    const float* __restrict__ Wo2,
                                    float* __restrict__ Wl1T,
                                    float* __restrict__ Wr1T,
                                    float* __restrict__ MlT,
                                    float* __restrict__ MrT,
                                    float* __restrict__ Wo2T)
{
    const int idx = blockIdx.x * 256 + threadIdx.x;   // 0 .. 65535
    const float* W; float* T; int local, logK;
    if (idx < 8192)        { W = Wl1; T = Wl1T; local = idx;         logK = 6; }
    else if (idx < 16384)  { W = Wr1; T = Wr1T; local = idx - 8192;  logK = 6; }
    else if (idx < 32768)  { W = Ml;  T = MlT;  local = idx - 16384; logK = 7; }
    else if (idx < 49152)  { W = Mr;  T = MrT;  local = idx - 32768; logK = 7; }
    else                   { W = Wo2; T = Wo2T; local = idx - 49152; logK = 7; }
    const int K = 1 << logK;
    const int n = local >> logK;
    const int k = local & (K - 1);
    T[n * K + k] = tf32r(W[k * EMB + n]);
}

// ---------------------------------------------------------------------------
// Launch
// ---------------------------------------------------------------------------
extern "C" void kernel_launch(void* const* d_in, const int* in_sizes, int n_in,
                              void* d_out, int out_size)
{
    const float* left  = (const float*)d_in[0];
    const int*   eidx  = (const int*)  d_in[1];
    const float* ew    = (const float*)d_in[2];
    const float* right = (const float*)d_in[3];
    const float* Wl1 = (const float*)d_in[5];
    const float* bl1 = (const float*)d_in[6];
    const float* Wl2 = (const float*)d_in[7];
    const float* bl2 = (const float*)d_in[8];
    const float* Wr1 = (const float*)d_in[9];
    const float* Wr2 = (const float*)d_in[10];
    const float* br2 = (const float*)d_in[11];
    const float* Wo1 = (const float*)d_in[12];
    const float* bo1 = (const float*)d_in[13];
    const float* Wo2 = (const float*)d_in[14];
    const float* bo2 = (const float*)d_in[15];

    const int nL = in_sizes[0] / 64;
    const int E  = in_sizes[1] / 2;
    const int nR = in_sizes[3] / 64;
    const int nO = out_size / EMB;

    float *gL, *gS, *gMl, *gMr, *gcl, *gcr;
    cudaGetSymbolAddress((void**)&gL,  g_L);
    cudaGetSymbolAddress((void**)&gS,  g_S);
    cudaGetSymbolAddress((void**)&gMl, g_Ml);
    cudaGetSymbolAddress((void**)&gMr, g_Mr);
    cudaGetSymbolAddress((void**)&gcl, g_cl);
    cudaGetSymbolAddress((void**)&gcr, g_cr);

    float *wl1t, *wr1t, *mlt, *mrt, *wo2t;
    cudaGetSymbolAddress((void**)&wl1t, g_Wl1T);
    cudaGetSymbolAddress((void**)&wr1t, g_Wr1T);
    cudaGetSymbolAddress((void**)&mlt,  g_MlT);
    cudaGetSymbolAddress((void**)&mrt,  g_MrT);
    cudaGetSymbolAddress((void**)&wo2t, g_Wo2T);

    cudaFuncSetAttribute(mlp2_kernel,     cudaFuncAttributeMaxDynamicSharedMemorySize, MLP_SMEM_BYTES);
    cudaFuncSetAttribute(out_gemm_kernel, cudaFuncAttributeMaxDynamicSharedMemorySize, F_SMEM_BYTES);

    const int gridL = (nL + 63) / 64;
    const int gridR = (nR + 63) / 64;
    const int gridO = (nO + 63) / 64;

    // launch 0-1: weight fold (matrix, bias)
    fuse_w_kernel<<<dim3(EMB, 2), EMB>>>(Wl2, Wr2, Wo1, gMl, gMr);
    fuse_b_kernel<<<2, EMB>>>(bl2, br2, Wo1, gcl, gcr);
    // launch 2: transpose + tf32 rounding (element-parallel)
    prep_weights_kernel<<<256, 256>>>(Wl1, Wr1, gMl, gMr, Wo2, wl1t, wr1t, mlt, mrt, wo2t);
    // launch 3 (profiler capture): merged MLP, both sides
    mlp2_kernel<<<gridL + gridR, 256, MLP_SMEM_BYTES>>>(
        left, right,
        (const uint4*)wl1t, (const uint4*)wr1t, bl1,
        (const uint4*)mlt, (const uint4*)mrt, gcl, gcr,
        gL, gS, nL, nR, gridL);
    // launch 4: edge-parallel scatter
    scatter_kernel<<<(E + 7) / 8, 256>>>(eidx, ew, gL, gS, E);
    // launch 5: output GEMM
    out_gemm_kernel<<<gridO, 256, F_SMEM_BYTES>>>(gS, (const uint4*)wo2t,
                                                  bo1, bo2, (float*)d_out, nO);
}

// round 14
// speedup vs baseline: 1.4474x; 1.1054x over previous
#include <cuda_runtime.h>
#include <cuda_bf16.h>
#include <cstdint>

// Problem constants (fixed by the dataset)
#define N_LEFT   100000
#define N_RIGHT  100000
#define N_EDGES  600000
#define EMB      128

// ---------------------------------------------------------------------------
// Device scratch (allocation-free rule: __device__ globals)
// ---------------------------------------------------------------------------
__device__ float g_L [N_LEFT  * EMB];   // transformed left (scatter source)
__device__ float g_S [N_RIGHT * EMB];   // transformed right + conv accumulator
__device__ float g_cl[EMB];
__device__ float g_cr[EMB];

// Pre-transposed tf32-rounded fp32 weight images, [n][k] k-contiguous (B^T).
__device__ __align__(16) float g_Wl1T[EMB * 64];
__device__ __align__(16) float g_Wr1T[EMB * 64];
__device__ __align__(16) float g_MlT [EMB * EMB];
__device__ __align__(16) float g_MrT [EMB * EMB];
__device__ __align__(16) float g_Wo2T[EMB * EMB];

// ---------------------------------------------------------------------------
// PTX helpers (all baseline sm_80+)
// ---------------------------------------------------------------------------
__device__ __forceinline__ void mma16808(float* d, const uint32_t* a, const uint32_t* b) {
    asm volatile(
        "mma.sync.aligned.m16n8k8.row.col.f32.tf32.tf32.f32 "
        "{%0,%1,%2,%3}, {%4,%5,%6,%7}, {%8,%9}, {%0,%1,%2,%3};"
        : "+f"(d[0]), "+f"(d[1]), "+f"(d[2]), "+f"(d[3])
        : "r"(a[0]), "r"(a[1]), "r"(a[2]), "r"(a[3]), "r"(b[0]), "r"(b[1]));
}
__device__ __forceinline__ void ldsm_x4(uint32_t& r0, uint32_t& r1, uint32_t& r2, uint32_t& r3,
                                        uint32_t addr) {
    asm volatile("ldmatrix.sync.aligned.m8n8.x4.shared.b16 {%0,%1,%2,%3}, [%4];"
                 : "=r"(r0), "=r"(r1), "=r"(r2), "=r"(r3) : "r"(addr));
}
__device__ __forceinline__ uint32_t cvta_s(const void* p) {
    return (uint32_t)__cvta_generic_to_shared(p);
}
__device__ __forceinline__ void cp_async16(uint32_t dst, const void* src) {
    asm volatile("cp.async.cg.shared.global [%0], [%1], 16;" :: "r"(dst), "l"(src));
}
__device__ __forceinline__ void cp_commit() {
    asm volatile("cp.async.commit_group;");
}
__device__ __forceinline__ void cp_wait0() {
    asm volatile("cp.async.wait_group 0;");
}
__device__ __forceinline__ float tf32r(float x) {
    uint32_t o;
    asm("cvt.rna.tf32.f32 %0, %1;" : "=r"(o) : "f"(x));
    return __uint_as_float(o);
}

// ---------------------------------------------------------------------------
// tf32 MMA stage: acc[MT][4][4] += A[MT*32][K] @ B[128][K]^T  (single pass)
// A, B fp32 (tf32-rounded) in smem, row stride K+4 floats (16B pad).
// ---------------------------------------------------------------------------
template<int K, int MT>
__device__ __forceinline__ void mma_stage(const float* __restrict__ A,
                                          const float* __restrict__ B,
                                          float acc[][4][4],
                                          int warp_m, int warp_n, int lane)
{
    constexpr int SK = K + 4;            // floats per row
    const int l7 = lane & 7;
    const int a_row = warp_m * (MT * 16) + l7 + ((lane >> 3) & 1) * 8;
    const uint32_t a_kb = (uint32_t)(lane >> 4) * 16;         // 0 or 16 bytes
    const int b_row = warp_n * 32 + l7 + (lane >> 4) * 8;
    const uint32_t b_kb = (uint32_t)((lane >> 3) & 1) * 16;

    uint32_t aA = cvta_s(A) + (uint32_t)(a_row * SK) * 4 + a_kb;
    uint32_t aB = cvta_s(B) + (uint32_t)(b_row * SK) * 4 + b_kb;

#pragma unroll
    for (int kc = 0; kc < K / 8; kc++) {
        const uint32_t ko = kc * 32;     // 8 tf32 = 32 bytes
        uint32_t a[MT][4], b[2][4];
#pragma unroll
        for (int mt = 0; mt < MT; mt++)
            ldsm_x4(a[mt][0], a[mt][1], a[mt][2], a[mt][3],
                    aA + (uint32_t)(mt * 16 * SK) * 4 + ko);
#pragma unroll
        for (int np = 0; np < 2; np++)
            ldsm_x4(b[np][0], b[np][1], b[np][2], b[np][3],
                    aB + (uint32_t)(np * 16 * SK) * 4 + ko);
#pragma unroll
        for (int mt = 0; mt < MT; mt++)
#pragma unroll
            for (int nt = 0; nt < 4; nt++)
                mma16808(acc[mt][nt], a[mt], &b[nt >> 1][(nt & 1) * 2]);
    }
}

// Async copy a [128][K] fp32 image from gmem (packed) into padded smem.
template<int K>
__device__ __forceinline__ void load_B_async(float* __restrict__ dst,
                                             const uint4* __restrict__ src, int tid)
{
    constexpr int SK = K + 4;
    constexpr int NV = 128 * K / 4;     // uint4 count
#pragma unroll
    for (int i = tid; i < NV; i += 256) {
        const int row = i / (K / 4);
        const int col = (i % (K / 4)) * 4;
        cp_async16(cvta_s(dst + row * SK + col), src + i);
    }
}

// Load A[row0..+63][0..K) fp32 from gmem, tf32-round, store padded smem.
template<int K>
__device__ __forceinline__ void load_A64(float* __restrict__ dst,
                                         const float* __restrict__ X,
                                         int row0, int M, int tid)
{
    constexpr int SK = K + 4;
    const int row  = tid >> 2;
    const int grow = row0 + row;
    const bool valid = grow < M;
    const float* xr = X + (size_t)grow * K;
    const int cbase = (tid & 3) * (K / 4);
#pragma unroll
    for (int q = 0; q < K / 16; q++) {
        const int c0 = cbase + q * 4;
        float4 v = valid ? *(const float4*)(xr + c0) : make_float4(0.f, 0.f, 0.f, 0.f);
        v.x = tf32r(v.x); v.y = tf32r(v.y); v.z = tf32r(v.z); v.w = tf32r(v.w);
        *(float4*)(dst + row * SK + c0) = v;
    }
}

// ---------------------------------------------------------------------------
// MERGED fused 2-layer MLP (left + right in one launch), M=64 per CTA,
// overlaid smem (2 CTAs/SM):  C = relu(X @ W1 [+ b1]) @ W2 + b2
// ---------------------------------------------------------------------------
#define K1 64
#define K2 128
#define SK1 (K1 + 4)                    // 68 floats
#define SK2 (K2 + 4)                    // 132 floats
#define ML_B1 0
#define ML_A1 (128 * SK1)               // 8704
#define ML_H  0
#define ML_B2 (128 * SK1)               // 8704 (overlays A1 region)
#define MLP_SMEM_FLOATS (ML_B2 + 128 * SK2)   // 25600
#define MLP_SMEM_BYTES (MLP_SMEM_FLOATS * 4)  // 102400

__global__ void __launch_bounds__(256, 2)
mlp2_kernel(const float* __restrict__ XL, const float* __restrict__ XR,
            const uint4* __restrict__ L_B1, const uint4* __restrict__ R_B1,
            const float* __restrict__ bl1,          // left stage-1 bias (right: none)
            const uint4* __restrict__ L_B2, const uint4* __restrict__ R_B2,
            const float* __restrict__ cl, const float* __restrict__ cr,
            float* __restrict__ CL, float* __restrict__ CR,
            int nL, int nR, int gridL)
{
    extern __shared__ float sm[];
    const int tid = threadIdx.x;
    const int wid = tid >> 5, lane = tid & 31;
    const int warp_m = wid >> 2, warp_n = wid & 3;
    const int g = lane >> 2, c = lane & 3;

    const bool leftSide = (blockIdx.x < gridL);
    const int  bidx  = leftSide ? blockIdx.x : blockIdx.x - gridL;
    const int  row0  = bidx * 64;
    const int  M     = leftSide ? nL : nR;
    const float* X   = leftSide ? XL : XR;
    const uint4* B1  = leftSide ? L_B1 : R_B1;
    const uint4* B2  = leftSide ? L_B2 : R_B2;
    const float* bias1 = leftSide ? bl1 : nullptr;
    const float* bias2 = leftSide ? cl : cr;
    float* C          = leftSide ? CL : CR;

    load_B_async<K1>(sm + ML_B1, B1, tid);
    cp_commit();
    load_A64<K1>(sm + ML_A1, X, row0, M, tid);   // overlaps B1 fetch
    cp_wait0();
    __syncthreads();

    float acc[2][4][4];
#pragma unroll
    for (int mt = 0; mt < 2; mt++)
#pragma unroll
        for (int nt = 0; nt < 4; nt++)
#pragma unroll
            for (int j = 0; j < 4; j++) acc[mt][nt][j] = 0.f;

    mma_stage<K1, 2>(sm + ML_A1, sm + ML_B1, acc, warp_m, warp_n, lane);
    __syncthreads();   // all warps done reading A1/B1

    // prefetch B2 over A1 region (consumed), overlapping epilogue-1
    load_B_async<K2>(sm + ML_B2, B2, tid);
    cp_commit();

    // epilogue 1: H = tf32(relu(acc + b1)) -> fp32 over B1 region
#pragma unroll
    for (int mt = 0; mt < 2; mt++) {
        const int row = warp_m * 32 + mt * 16 + g;
#pragma unroll
        for (int nt = 0; nt < 4; nt++) {
            const int col = warp_n * 32 + nt * 8 + c * 2;
            float v0 = acc[mt][nt][0], v1 = acc[mt][nt][1];
            float v2 = acc[mt][nt][2], v3 = acc[mt][nt][3];
            if (bias1) {
                float2 b = *(const float2*)(bias1 + col);
                v0 += b.x; v1 += b.y; v2 += b.x; v3 += b.y;
            }
            float2 p0 = make_float2(tf32r(fmaxf(v0, 0.f)), tf32r(fmaxf(v1, 0.f)));
            float2 p1 = make_float2(tf32r(fmaxf(v2, 0.f)), tf32r(fmaxf(v3, 0.f)));
            *(float2*)(sm + ML_H + row * SK2 + col)       = p0;
            *(float2*)(sm + ML_H + (row + 8) * SK2 + col) = p1;
        }
    }
    cp_wait0();
    __syncthreads();

#pragma unroll
    for (int mt = 0; mt < 2; mt++)
#pragma unroll
        for (int nt = 0; nt < 4; nt++)
#pragma unroll
            for (int j = 0; j < 4; j++) acc[mt][nt][j] = 0.f;

    mma_stage<K2, 2>(sm + ML_H, sm + ML_B2, acc, warp_m, warp_n, lane);

#pragma unroll
    for (int mt = 0; mt < 2; mt++) {
        const int r = row0 + warp_m * 32 + mt * 16 + g;
#pragma unroll
        for (int nt = 0; nt < 4; nt++) {
            const int col = warp_n * 32 + nt * 8 + c * 2;
            float2 b = *(const float2*)(bias2 + col);
            if (r < M) {
                float2 o0 = make_float2(acc[mt][nt][0] + b.x, acc[mt][nt][1] + b.y);
                *(float2*)(C + (size_t)r * EMB + col) = o0;
            }
            if (r + 8 < M) {
                float2 o1 = make_float2(acc[mt][nt][2] + b.x, acc[mt][nt][3] + b.y);
                *(float2*)(C + (size_t)(r + 8) * EMB + col) = o1;
            }
        }
    }
}

// ---------------------------------------------------------------------------
// Edge scatter: one warp per TWO edges (higher MLP).  S[dst] += w_e * L[src]
// ---------------------------------------------------------------------------
__global__ void scatter_kernel(const int* __restrict__ eidx,
                               const float* __restrict__ ew,
                               const float* __restrict__ L,
                               float* __restrict__ S,
                               int E)
{
    const int warp = (blockIdx.x * blockDim.x + threadIdx.x) >> 5;
    const int lane = threadIdx.x & 31;
    const int e0 = warp * 2;
    if (e0 >= E) return;
    const int e1 = e0 + 1;
    const bool has1 = (e1 < E);

    const int   src0 = eidx[e0];
    const int   dst0 = eidx[E + e0];
    const float w0   = ew[e0];
    const int   src1 = has1 ? eidx[e1]     : src0;
    const int   dst1 = has1 ? eidx[E + e1] : dst0;
    const float w1   = has1 ? ew[e1]       : 0.f;

    // two independent row loads in flight
    const float4 v0 = *(const float4*)(L + (size_t)src0 * EMB + lane * 4);
    const float4 v1 = *(const float4*)(L + (size_t)src1 * EMB + lane * 4);

    float* o0 = S + (size_t)dst0 * EMB + lane * 4;
    asm volatile("red.global.add.v4.f32 [%0], {%1, %2, %3, %4};"
                 :: "l"(o0), "f"(w0 * v0.x), "f"(w0 * v0.y), "f"(w0 * v0.z), "f"(w0 * v0.w)
                 : "memory");
    if (has1) {
        float* o1 = S + (size_t)dst1 * EMB + lane * 4;
        asm volatile("red.global.add.v4.f32 [%0], {%1, %2, %3, %4};"
                     :: "l"(o1), "f"(w1 * v1.x), "f"(w1 * v1.y), "f"(w1 * v1.z), "f"(w1 * v1.w)
                     : "memory");
    }
}

// ---------------------------------------------------------------------------
// Output GEMM, M=64 per CTA (2 CTAs/SM):  out = relu(S + bo1) @ Wo2 + bo2
// ---------------------------------------------------------------------------
#define F_A 0
#define F_B (64 * SK2)                        // 8448
#define F_SMEM_FLOATS (F_B + 128 * SK2)       // 25344
#define F_SMEM_BYTES (F_SMEM_FLOATS * 4)      // 101376

__global__ void __launch_bounds__(256, 2)
out_gemm_kernel(const float* __restrict__ S,
                const uint4* __restrict__ Bimg,
                const float* __restrict__ bo1,
                const float* __restrict__ bo2,
                float* __restrict__ C, int M)
{
    extern __shared__ float sm[];
    const int tid = threadIdx.x;
    const int wid = tid >> 5, lane = tid & 31;
    const int warp_m = wid >> 2, warp_n = wid & 3;
    const int g = lane >> 2, c = lane & 3;
    const int row0 = blockIdx.x * 64;

    load_B_async<K2>(sm + F_B, Bimg, tid);
    cp_commit();

    // A-load: tf32(relu(S + bo1)), store (overlaps B fetch)
    {
        const int row  = tid >> 2;
        const int grow = row0 + row;
        const bool valid = grow < M;
        const float* sr = S + (size_t)grow * K2;
        const int cbase = (tid & 3) * (K2 / 4);
#pragma unroll
        for (int q = 0; q < K2 / 16; q++) {
            const int c0 = cbase + q * 4;
            float4 v = make_float4(0.f, 0.f, 0.f, 0.f);
            if (valid) {
                float4 a = *(const float4*)(sr + c0);
                float4 pb = *(const float4*)(bo1 + c0);
                v.x = tf32r(fmaxf(a.x + pb.x, 0.f));
                v.y = tf32r(fmaxf(a.y + pb.y, 0.f));
                v.z = tf32r(fmaxf(a.z + pb.z, 0.f));
                v.w = tf32r(fmaxf(a.w + pb.w, 0.f));
            }
            *(float4*)(sm + F_A + row * SK2 + c0) = v;
        }
    }
    cp_wait0();
    __syncthreads();

    float acc[2][4][4];
#pragma unroll
    for (int mt = 0; mt < 2; mt++)
#pragma unroll
        for (int nt = 0; nt < 4; nt++)
#pragma unroll
            for (int j = 0; j < 4; j++) acc[mt][nt][j] = 0.f;

    mma_stage<K2, 2>(sm + F_A, sm + F_B, acc, warp_m, warp_n, lane);

#pragma unroll
    for (int mt = 0; mt < 2; mt++) {
        const int r = row0 + warp_m * 32 + mt * 16 + g;
#pragma unroll
        for (int nt = 0; nt < 4; nt++) {
            const int col = warp_n * 32 + nt * 8 + c * 2;
            float2 b = *(const float2*)(bo2 + col);
            if (r < M) {
                float2 o0 = make_float2(acc[mt][nt][0] + b.x, acc[mt][nt][1] + b.y);
                *(float2*)(C + (size_t)r * EMB + col) = o0;
            }
            if (r + 8 < M) {
                float2 o1 = make_float2(acc[mt][nt][2] + b.x, acc[mt][nt][3] + b.y);
                *(float2*)(C + (size_t)(r + 8) * EMB + col) = o1;
            }
        }
    }
}

// ---------------------------------------------------------------------------
// ALL weight prep in ONE launch:
//   blocks [0,256):    fused fold  MlT/MrT[j][i] = tf32(sum_k W2[i][k]*Wo1[off+k][j])
//                      (Ml/Mr never materialized; written directly transposed)
//   block  256:        bias rows   cl/cr[j] = sum_k b[k]*Wo1[off+k][j]
//   blocks [257,385):  transpose + tf32 of Wl1 / Wr1 / Wo2 (32768 elements)
// ---------------------------------------------------------------------------
__global__ void prep_all_kernel(const float* __restrict__ Wl1,
                                const float* __restrict__ Wr1,
                                const float* __restrict__ Wl2,
                                const float* __restrict__ Wr2,
                                const float* __restrict__ bl2,
                                const float* __restrict__ br2,
                                const float* __restrict__ Wo1,
                                const float* __restrict__ Wo2,
                                float* __restrict__ Wl1T,
                                float* __restrict__ Wr1T,
                                float* __restrict__ MlT,
                                float* __restrict__ MrT,
                                float* __restrict__ Wo2T,
                                float* __restrict__ cl,
                                float* __restrict__ cr)
{
    const int b = blockIdx.x;
    const int j = threadIdx.x;          // 0..255
    if (b < 256) {
        // fold: side rs, matrix row i, output col (j & 127)
        const bool rs = (b >= 128);
        const int i  = b & 127;
        if (j >= 128) return;
        const int off = rs ? EMB : 0;
        const float* vec = (rs ? Wr2 : Wl2) + i * EMB;
        float s = 0.f;
#pragma unroll 8
        for (int k = 0; k < EMB; k++)
            s += vec[k] * Wo1[(off + k) * EMB + j];
        (rs ? MrT : MlT)[j * EMB + i] = tf32r(s);   // write transposed B^T image
    } else if (b == 256) {
        const bool rs = (j >= 128);
        const int jj = j & 127;
        const float* bb = rs ? br2 : bl2;
        const int off = rs ? EMB : 0;
        float s = 0.f;
#pragma unroll 8
        for (int k = 0; k < EMB; k++)
            s += bb[k] * Wo1[(off + k) * EMB + jj];
        (rs ? cr : cl)[jj] = s;
    } else {
        const int idx = (b - 257) * 256 + j;        // 0 .. 32767
        const float* W; float* T; int local, logK;
        if (idx < 8192)       { W = Wl1; T = Wl1T; local = idx;         logK = 6; }
        else if (idx < 16384) { W = Wr1; T = Wr1T; local = idx - 8192;  logK = 6; }
        else                  { W = Wo2; T = Wo2T; local = idx - 16384; logK = 7; }
        const int K = 1 << logK;
        const int n = local >> logK;
        const int k = local & (K - 1);
        T[n * K + k] = tf32r(W[k * EMB + n]);
    }
}

// ---------------------------------------------------------------------------
// Launch
// ---------------------------------------------------------------------------
extern "C" void kernel_launch(void* const* d_in, const int* in_sizes, int n_in,
                              void* d_out, int out_size)
{
    const float* left  = (const float*)d_in[0];
    const int*   eidx  = (const int*)  d_in[1];
    const float* ew    = (const float*)d_in[2];
    const float* right = (const float*)d_in[3];
    const float* Wl1 = (const float*)d_in[5];
    const float* bl1 = (const float*)d_in[6];
    const float* Wl2 = (const float*)d_in[7];
    const float* bl2 = (const float*)d_in[8];
    const float* Wr1 = (const float*)d_in[9];
    const float* Wr2 = (const float*)d_in[10];
    const float* br2 = (const float*)d_in[11];
    const float* Wo1 = (const float*)d_in[12];
    const float* bo1 = (const float*)d_in[13];
    const float* Wo2 = (const float*)d_in[14];
    const float* bo2 = (const float*)d_in[15];

    const int nL = in_sizes[0] / 64;
    const int E  = in_sizes[1] / 2;
    const int nR = in_sizes[3] / 64;
    const int nO = out_size / EMB;

    float *gL, *gS, *gcl, *gcr;
    cudaGetSymbolAddress((void**)&gL,  g_L);
    cudaGetSymbolAddress((void**)&gS,  g_S);
    cudaGetSymbolAddress((void**)&gcl, g_cl);
    cudaGetSymbolAddress((void**)&gcr, g_cr);

    float *wl1t, *wr1t, *mlt, *mrt, *wo2t;
    cudaGetSymbolAddress((void**)&wl1t, g_Wl1T);
    cudaGetSymbolAddress((void**)&wr1t, g_Wr1T);
    cudaGetSymbolAddress((void**)&mlt,  g_MlT);
    cudaGetSymbolAddress((void**)&mrt,  g_MrT);
    cudaGetSymbolAddress((void**)&wo2t, g_Wo2T);

    cudaFuncSetAttribute(mlp2_kernel,     cudaFuncAttributeMaxDynamicSharedMemorySize, MLP_SMEM_BYTES);
    cudaFuncSetAttribute(out_gemm_kernel, cudaFuncAttributeMaxDynamicSharedMemorySize, F_SMEM_BYTES);

    const int gridL = (nL + 63) / 64;
    const int gridR = (nR + 63) / 64;
    const int gridO = (nO + 63) / 64;

    // launch 0: ALL weight prep (fold + bias + transpose, one kernel)
    prep_all_kernel<<<385, 256>>>(Wl1, Wr1, Wl2, Wr2, bl2, br2, Wo1, Wo2,
                                  wl1t, wr1t, mlt, mrt, wo2t, gcl, gcr);
    // launch 1: merged MLP, both sides
    mlp2_kernel<<<gridL + gridR, 256, MLP_SMEM_BYTES>>>(
        left, right,
        (const uint4*)wl1t, (const uint4*)wr1t, bl1,
        (const uint4*)mlt, (const uint4*)mrt, gcl, gcr,
        gL, gS, nL, nR, gridL);
    // launch 2: edge-parallel scatter (2 edges per warp)
    scatter_kernel<<<(E + 15) / 16, 256>>>(eidx, ew, gL, gS, E);
    // launch 3 (profiler capture): output GEMM
    out_gemm_kernel<<<gridO, 256, F_SMEM_BYTES>>>(gS, (const uint4*)wo2t,
                                                  bo1, bo2, (float*)d_out, nO);
}